// round 1
// baseline (speedup 1.0000x reference)
#include <cuda_runtime.h>
#include <math.h>

#define BSZ   512
#define LEN   100
#define NCAND 64
#define DIM   256
#define KIN   32

// Scratch (no allocations allowed): 52.4 MB + 16.8 MB
__device__ float g_proj[BSZ * LEN * DIM];
__device__ float g_inter[BSZ * KIN * DIM];

// ---------------------------------------------------------------------------
// K1: proj = tanh(hist @ W^T)   [M=51200, N=256, K=256]
// Classic 128x128x16 fp32 SGEMM, 256 threads, 8x8 per thread. Exact tiling.
// ---------------------------------------------------------------------------
__global__ __launch_bounds__(256) void k1_proj_kernel(const float* __restrict__ A,
                                                      const float* __restrict__ W) {
    __shared__ float As[16][132];   // As[k][m], padded
    __shared__ float Bs[16][132];   // Bs[k][n] = W[n][k], padded

    const int tid = threadIdx.x;
    const int m0  = blockIdx.y * 128;
    const int n0  = blockIdx.x * 128;
    const int tx  = tid & 15;          // n-dir
    const int ty  = tid >> 4;          // m-dir
    const int ar  = tid >> 2;          // 0..63 (A row)
    const int ac  = (tid & 3) << 2;    // 0,4,8,12 (A k-offset)
    const int bn  = tid & 127;         // B column (c)
    const int bk  = (tid >> 7) << 3;   // 0 or 8 (B k-offset)

    float acc[8][8];
#pragma unroll
    for (int i = 0; i < 8; i++)
#pragma unroll
        for (int j = 0; j < 8; j++) acc[i][j] = 0.f;

    for (int k0 = 0; k0 < 256; k0 += 16) {
        float4 a0 = *(const float4*)&A[(size_t)(m0 + ar) * 256 + k0 + ac];
        float4 a1 = *(const float4*)&A[(size_t)(m0 + ar + 64) * 256 + k0 + ac];
        As[ac + 0][ar] = a0.x; As[ac + 1][ar] = a0.y;
        As[ac + 2][ar] = a0.z; As[ac + 3][ar] = a0.w;
        As[ac + 0][ar + 64] = a1.x; As[ac + 1][ar + 64] = a1.y;
        As[ac + 2][ar + 64] = a1.z; As[ac + 3][ar + 64] = a1.w;

        float4 b0 = *(const float4*)&W[(size_t)(n0 + bn) * 256 + k0 + bk];
        float4 b1 = *(const float4*)&W[(size_t)(n0 + bn) * 256 + k0 + bk + 4];
        Bs[bk + 0][bn] = b0.x; Bs[bk + 1][bn] = b0.y;
        Bs[bk + 2][bn] = b0.z; Bs[bk + 3][bn] = b0.w;
        Bs[bk + 4][bn] = b1.x; Bs[bk + 5][bn] = b1.y;
        Bs[bk + 6][bn] = b1.z; Bs[bk + 7][bn] = b1.w;
        __syncthreads();

#pragma unroll
        for (int kk = 0; kk < 16; kk++) {
            float ra[8], rb[8];
            *(float4*)&ra[0] = *(const float4*)&As[kk][ty * 8];
            *(float4*)&ra[4] = *(const float4*)&As[kk][ty * 8 + 4];
            *(float4*)&rb[0] = *(const float4*)&Bs[kk][tx * 8];
            *(float4*)&rb[4] = *(const float4*)&Bs[kk][tx * 8 + 4];
#pragma unroll
            for (int i = 0; i < 8; i++)
#pragma unroll
                for (int j = 0; j < 8; j++) acc[i][j] = fmaf(ra[i], rb[j], acc[i][j]);
        }
        __syncthreads();
    }

#pragma unroll
    for (int i = 0; i < 8; i++) {
        const size_t row = (size_t)(m0 + ty * 8 + i);
        float4 v0, v1;
        v0.x = tanhf(acc[i][0]); v0.y = tanhf(acc[i][1]);
        v0.z = tanhf(acc[i][2]); v0.w = tanhf(acc[i][3]);
        v1.x = tanhf(acc[i][4]); v1.y = tanhf(acc[i][5]);
        v1.z = tanhf(acc[i][6]); v1.w = tanhf(acc[i][7]);
        *(float4*)&g_proj[row * 256 + n0 + tx * 8]     = v0;
        *(float4*)&g_proj[row * 256 + n0 + tx * 8 + 4] = v1;
    }
}

// ---------------------------------------------------------------------------
// K2: per-batch  scores -> mask -> softmax(L) -> interests
// One block per b, 256 threads.
//   scores[k,l] = sum_c proj[b,l,c] * codes[k,c]  (warp w owns c-chunk, lane=k)
//   masked k (k >= numInt): all scores = -1e9 -> softmax uniform = 1/100 exactly
//   interests[k,d] = sum_l attn[k,l] * hist[b,l,d] (thread=d, 32 k-accumulators)
// ---------------------------------------------------------------------------
__global__ __launch_bounds__(256) void k2_kernel(const float* __restrict__ hist,
                                                 const float* __restrict__ codes,
                                                 const int* __restrict__ numInt) {
    const int b = blockIdx.x;
    const int tid = threadIdx.x;
    const int w = tid >> 5;      // warp = c-chunk
    const int lane = tid & 31;   // lane = k

    __shared__ float row_sm[4][256];
    __shared__ float partial_sm[8][4][32];
    __shared__ float scores_sm[32][100];
    __shared__ float attnT_sm[100][32];

    // context-code chunk -> registers (codes is 32KB, L2 resident)
    float creg[32];
#pragma unroll
    for (int j = 0; j < 32; j++) creg[j] = codes[lane * 256 + w * 32 + j];

    const float* Pb = g_proj + (size_t)b * LEN * DIM;
    for (int l0 = 0; l0 < LEN; l0 += 4) {
#pragma unroll
        for (int r = 0; r < 4; r++) row_sm[r][tid] = Pb[(l0 + r) * 256 + tid];
        __syncthreads();

        float p0 = 0.f, p1 = 0.f, p2 = 0.f, p3 = 0.f;
#pragma unroll
        for (int j4 = 0; j4 < 8; j4++) {
            float4 r0 = *(const float4*)&row_sm[0][w * 32 + j4 * 4];
            float4 r1 = *(const float4*)&row_sm[1][w * 32 + j4 * 4];
            float4 r2 = *(const float4*)&row_sm[2][w * 32 + j4 * 4];
            float4 r3 = *(const float4*)&row_sm[3][w * 32 + j4 * 4];
            const float c0 = creg[j4 * 4 + 0], c1 = creg[j4 * 4 + 1];
            const float c2 = creg[j4 * 4 + 2], c3 = creg[j4 * 4 + 3];
            p0 = fmaf(r0.x, c0, p0); p0 = fmaf(r0.y, c1, p0);
            p0 = fmaf(r0.z, c2, p0); p0 = fmaf(r0.w, c3, p0);
            p1 = fmaf(r1.x, c0, p1); p1 = fmaf(r1.y, c1, p1);
            p1 = fmaf(r1.z, c2, p1); p1 = fmaf(r1.w, c3, p1);
            p2 = fmaf(r2.x, c0, p2); p2 = fmaf(r2.y, c1, p2);
            p2 = fmaf(r2.z, c2, p2); p2 = fmaf(r2.w, c3, p2);
            p3 = fmaf(r3.x, c0, p3); p3 = fmaf(r3.y, c1, p3);
            p3 = fmaf(r3.z, c2, p3); p3 = fmaf(r3.w, c3, p3);
        }
        partial_sm[w][0][lane] = p0;
        partial_sm[w][1][lane] = p1;
        partial_sm[w][2][lane] = p2;
        partial_sm[w][3][lane] = p3;
        __syncthreads();

        if (tid < 128) {
            const int k = tid & 31, r = tid >> 5;
            float s = 0.f;
#pragma unroll
            for (int ww = 0; ww < 8; ww++) s += partial_sm[ww][r][k];
            scores_sm[k][l0 + r] = s;
        }
        __syncthreads();
    }

    // softmax over L per interest code (warp per k, 4 rounds)
    const int ni = numInt[b];
    for (int k = w; k < 32; k += 8) {
        if (k >= ni) {
            // reference: scores all -1e9 -> softmax uniform = 1/100
            for (int l = lane; l < LEN; l += 32) scores_sm[k][l] = 0.01f;
        } else {
            float m = -3.4e38f;
            for (int l = lane; l < LEN; l += 32) m = fmaxf(m, scores_sm[k][l]);
#pragma unroll
            for (int off = 16; off; off >>= 1)
                m = fmaxf(m, __shfl_xor_sync(0xffffffffu, m, off));
            float s = 0.f;
            for (int l = lane; l < LEN; l += 32) {
                float e = expf(scores_sm[k][l] - m);
                scores_sm[k][l] = e;
                s += e;
            }
#pragma unroll
            for (int off = 16; off; off >>= 1) s += __shfl_xor_sync(0xffffffffu, s, off);
            for (int l = lane; l < LEN; l += 32) scores_sm[k][l] = scores_sm[k][l] / s;
        }
    }
    __syncthreads();

    // transpose attn for float4 broadcast reads in the interests phase
    for (int idx = tid; idx < LEN * 32; idx += 256) {
        const int l = idx >> 5, k = idx & 31;
        attnT_sm[l][k] = scores_sm[k][l];
    }
    __syncthreads();

    // interests[k, d=tid] = sum_l attn[k,l]*hist[l,tid]
    float accI[32];
#pragma unroll
    for (int k = 0; k < 32; k++) accI[k] = 0.f;

    const float* Hb = hist + (size_t)b * LEN * DIM;
    float hv = Hb[tid];
    for (int l = 0; l < LEN; l++) {
        const float hn = (l + 1 < LEN) ? Hb[(l + 1) * 256 + tid] : 0.f;
#pragma unroll
        for (int k4 = 0; k4 < 8; k4++) {
            float4 a = *(const float4*)&attnT_sm[l][k4 * 4];
            accI[k4 * 4 + 0] = fmaf(a.x, hv, accI[k4 * 4 + 0]);
            accI[k4 * 4 + 1] = fmaf(a.y, hv, accI[k4 * 4 + 1]);
            accI[k4 * 4 + 2] = fmaf(a.z, hv, accI[k4 * 4 + 2]);
            accI[k4 * 4 + 3] = fmaf(a.w, hv, accI[k4 * 4 + 3]);
        }
        hv = hn;
    }
    float* Ib = g_inter + (size_t)b * KIN * DIM;
#pragma unroll
    for (int k = 0; k < 32; k++) Ib[k * 256 + tid] = accI[k];
}

// ---------------------------------------------------------------------------
// K4: per-batch  w = cand·interests^T -> dynK top-k mask -> user = (w*mask)·interests
// One block per b, 256 threads.
// ---------------------------------------------------------------------------
__global__ __launch_bounds__(256) void k4_kernel(const float* __restrict__ cand,
                                                 const int* __restrict__ catCnt,
                                                 float* __restrict__ out) {
    const int b = blockIdx.x;
    const int tid = threadIdx.x;
    const int w = tid >> 5;
    const int lane = tid & 31;

    __shared__ float inter_sm[32][256];
    __shared__ float row_sm[2][256];
    __shared__ float partial_sm[8][2][32];
    __shared__ float wfull_sm[2][32];
    __shared__ float wmask_sm[32][64];

    const float* Ib = g_inter + (size_t)b * KIN * DIM;
    for (int idx = tid; idx < 32 * 256; idx += 256)
        inter_sm[idx >> 8][idx & 255] = Ib[idx];
    __syncthreads();

    float ireg[32];
#pragma unroll
    for (int j = 0; j < 32; j++) ireg[j] = inter_sm[lane][w * 32 + j];

    const int cc = catCnt[b];
    int dynK = (int)ceilf(log2f(8.0f * (float)cc));
    dynK = dynK < 1 ? 1 : (dynK > 32 ? 32 : dynK);

    const float* Cb = cand + (size_t)b * NCAND * DIM;
    for (int n0 = 0; n0 < NCAND; n0 += 2) {
        row_sm[0][tid] = Cb[(size_t)n0 * 256 + tid];
        row_sm[1][tid] = Cb[(size_t)(n0 + 1) * 256 + tid];
        __syncthreads();

        float p0 = 0.f, p1 = 0.f;
#pragma unroll
        for (int j4 = 0; j4 < 8; j4++) {
            float4 r0 = *(const float4*)&row_sm[0][w * 32 + j4 * 4];
            float4 r1 = *(const float4*)&row_sm[1][w * 32 + j4 * 4];
            const float i0 = ireg[j4 * 4 + 0], i1 = ireg[j4 * 4 + 1];
            const float i2 = ireg[j4 * 4 + 2], i3 = ireg[j4 * 4 + 3];
            p0 = fmaf(r0.x, i0, p0); p0 = fmaf(r0.y, i1, p0);
            p0 = fmaf(r0.z, i2, p0); p0 = fmaf(r0.w, i3, p0);
            p1 = fmaf(r1.x, i0, p1); p1 = fmaf(r1.y, i1, p1);
            p1 = fmaf(r1.z, i2, p1); p1 = fmaf(r1.w, i3, p1);
        }
        partial_sm[w][0][lane] = p0;
        partial_sm[w][1][lane] = p1;
        __syncthreads();

        if (tid < 64) {
            const int k = tid & 31, r = tid >> 5;
            float s = 0.f;
#pragma unroll
            for (int ww = 0; ww < 8; ww++) s += partial_sm[ww][r][k];
            wfull_sm[r][k] = s;
        }
        __syncthreads();

        if (w < 2) {
            const float wi = wfull_sm[w][lane];
            int rank = 0;
#pragma unroll
            for (int j = 0; j < 32; j++) {
                const float wj = __shfl_sync(0xffffffffu, wi, j);
                // reference tie-break: stable argsort(-w) -> lower index wins ties
                rank += (wj > wi) || (wj == wi && j < lane);
            }
            wmask_sm[lane][n0 + w] = (rank < dynK) ? wi : 0.f;
        }
        __syncthreads();
    }

    // user[n, d=tid] = sum_k wmask[n,k] * interests[k,tid]
    float accU[64];
#pragma unroll
    for (int n = 0; n < 64; n++) accU[n] = 0.f;

#pragma unroll
    for (int k = 0; k < 32; k++) {
        const float iv = inter_sm[k][tid];
#pragma unroll
        for (int n4 = 0; n4 < 16; n4++) {
            float4 wv = *(const float4*)&wmask_sm[k][n4 * 4];
            accU[n4 * 4 + 0] = fmaf(wv.x, iv, accU[n4 * 4 + 0]);
            accU[n4 * 4 + 1] = fmaf(wv.y, iv, accU[n4 * 4 + 1]);
            accU[n4 * 4 + 2] = fmaf(wv.z, iv, accU[n4 * 4 + 2]);
            accU[n4 * 4 + 3] = fmaf(wv.w, iv, accU[n4 * 4 + 3]);
        }
    }

    float* Ob = out + (size_t)b * NCAND * DIM;
#pragma unroll
    for (int n = 0; n < 64; n++) Ob[(size_t)n * 256 + tid] = accU[n];
}

// ---------------------------------------------------------------------------
extern "C" void kernel_launch(void* const* d_in, const int* in_sizes, int n_in,
                              void* d_out, int out_size) {
    (void)in_sizes; (void)n_in; (void)out_size;
    const float* hist  = (const float*)d_in[0];
    // d_in[1] = history_mask (unused by reference forward)
    const float* cand  = (const float*)d_in[2];
    const int*   numI  = (const int*)d_in[3];
    const int*   catC  = (const int*)d_in[4];
    const float* W     = (const float*)d_in[5];
    const float* codes = (const float*)d_in[6];
    float* out = (float*)d_out;

    k1_proj_kernel<<<dim3(2, 400), 256>>>(hist, W);
    k2_kernel<<<BSZ, 256>>>(hist, codes, numI);
    k4_kernel<<<BSZ, 256>>>(cand, catC, out);
}

// round 2
// speedup vs baseline: 1.1735x; 1.1735x over previous
#include <cuda_runtime.h>
#include <math.h>

#define BSZ   512
#define LEN   100
#define NCAND 64
#define DIM   256
#define KIN   32

typedef unsigned long long u64;

// Scratch (no allocations allowed)
__device__ float g_proj[BSZ * LEN * DIM];
__device__ float g_inter[BSZ * KIN * DIM];

// ---- packed fp32x2 helpers (Blackwell sm_103a) ------------------------------
__device__ __forceinline__ u64 ffma2(u64 a, u64 b, u64 c) {
    u64 d;
    asm("fma.rn.f32x2 %0, %1, %2, %3;" : "=l"(d) : "l"(a), "l"(b), "l"(c));
    return d;
}
__device__ __forceinline__ u64 pack2(float lo, float hi) {
    u64 r;
    asm("mov.b64 %0, {%1, %2};" : "=l"(r) : "f"(lo), "f"(hi));
    return r;
}
__device__ __forceinline__ float2 unpack2(u64 v) {
    float2 r;
    asm("mov.b64 {%0, %1}, %2;" : "=f"(r.x), "=f"(r.y) : "l"(v));
    return r;
}

// ---------------------------------------------------------------------------
// K1: proj = tanh(hist @ W^T)   [M=51200, N=256, K=256]
// 128x128x16 tiles, 8x8 per thread, f32x2 packed accumulators (pairs along n),
// register prefetch of next k-tile.
// ---------------------------------------------------------------------------
__global__ __launch_bounds__(256, 2) void k1_proj_kernel(const float* __restrict__ A,
                                                         const float* __restrict__ W) {
    __shared__ __align__(16) float As[16][132];   // As[k][m]
    __shared__ __align__(16) float Bs[16][132];   // Bs[k][n] = W[n][k]

    const int tid = threadIdx.x;
    const int m0  = blockIdx.y * 128;
    const int n0  = blockIdx.x * 128;
    const int tx  = tid & 15;          // n-dir
    const int ty  = tid >> 4;          // m-dir
    const int ar  = tid >> 2;          // 0..63 (A row)
    const int ac  = (tid & 3) << 2;    // 0,4,8,12 (A k-offset)
    const int bn  = tid & 127;         // B column (c)
    const int bk  = (tid >> 7) << 3;   // 0 or 8 (B k-offset)

    u64 acc[8][4];
#pragma unroll
    for (int i = 0; i < 8; i++)
#pragma unroll
        for (int j = 0; j < 4; j++) acc[i][j] = 0ull;

    // prologue prefetch (k0 = 0)
    float4 pa0 = *(const float4*)&A[(size_t)(m0 + ar) * 256 + ac];
    float4 pa1 = *(const float4*)&A[(size_t)(m0 + ar + 64) * 256 + ac];
    float4 pb0 = *(const float4*)&W[(size_t)(n0 + bn) * 256 + bk];
    float4 pb1 = *(const float4*)&W[(size_t)(n0 + bn) * 256 + bk + 4];

    for (int k0 = 0; k0 < 256; k0 += 16) {
        As[ac + 0][ar] = pa0.x; As[ac + 1][ar] = pa0.y;
        As[ac + 2][ar] = pa0.z; As[ac + 3][ar] = pa0.w;
        As[ac + 0][ar + 64] = pa1.x; As[ac + 1][ar + 64] = pa1.y;
        As[ac + 2][ar + 64] = pa1.z; As[ac + 3][ar + 64] = pa1.w;
        Bs[bk + 0][bn] = pb0.x; Bs[bk + 1][bn] = pb0.y;
        Bs[bk + 2][bn] = pb0.z; Bs[bk + 3][bn] = pb0.w;
        Bs[bk + 4][bn] = pb1.x; Bs[bk + 5][bn] = pb1.y;
        Bs[bk + 6][bn] = pb1.z; Bs[bk + 7][bn] = pb1.w;
        __syncthreads();

        if (k0 + 16 < 256) {
            const int kn = k0 + 16;
            pa0 = *(const float4*)&A[(size_t)(m0 + ar) * 256 + kn + ac];
            pa1 = *(const float4*)&A[(size_t)(m0 + ar + 64) * 256 + kn + ac];
            pb0 = *(const float4*)&W[(size_t)(n0 + bn) * 256 + kn + bk];
            pb1 = *(const float4*)&W[(size_t)(n0 + bn) * 256 + kn + bk + 4];
        }

#pragma unroll
        for (int kk = 0; kk < 16; kk++) {
            float4 ra0 = *(const float4*)&As[kk][ty * 8];
            float4 ra1 = *(const float4*)&As[kk][ty * 8 + 4];
            const u64* bp = (const u64*)&Bs[kk][tx * 8];
            const u64 rb0 = bp[0], rb1 = bp[1], rb2 = bp[2], rb3 = bp[3];

            u64 ra[8];
            ra[0] = pack2(ra0.x, ra0.x); ra[1] = pack2(ra0.y, ra0.y);
            ra[2] = pack2(ra0.z, ra0.z); ra[3] = pack2(ra0.w, ra0.w);
            ra[4] = pack2(ra1.x, ra1.x); ra[5] = pack2(ra1.y, ra1.y);
            ra[6] = pack2(ra1.z, ra1.z); ra[7] = pack2(ra1.w, ra1.w);
#pragma unroll
            for (int i = 0; i < 8; i++) {
                acc[i][0] = ffma2(ra[i], rb0, acc[i][0]);
                acc[i][1] = ffma2(ra[i], rb1, acc[i][1]);
                acc[i][2] = ffma2(ra[i], rb2, acc[i][2]);
                acc[i][3] = ffma2(ra[i], rb3, acc[i][3]);
            }
        }
        __syncthreads();
    }

#pragma unroll
    for (int i = 0; i < 8; i++) {
        const size_t row = (size_t)(m0 + ty * 8 + i);
        float2 t0 = unpack2(acc[i][0]);
        float2 t1 = unpack2(acc[i][1]);
        float2 t2 = unpack2(acc[i][2]);
        float2 t3 = unpack2(acc[i][3]);
        float4 v0, v1;
        v0.x = tanhf(t0.x); v0.y = tanhf(t0.y);
        v0.z = tanhf(t1.x); v0.w = tanhf(t1.y);
        v1.x = tanhf(t2.x); v1.y = tanhf(t2.y);
        v1.z = tanhf(t3.x); v1.w = tanhf(t3.y);
        *(float4*)&g_proj[row * 256 + n0 + tx * 8]     = v0;
        *(float4*)&g_proj[row * 256 + n0 + tx * 8 + 4] = v1;
    }
}

// ---------------------------------------------------------------------------
// K2: per-batch  scores -> mask -> softmax(L) -> interests
// 8 L-rows per iteration, packed f32x2 throughout.
// ---------------------------------------------------------------------------
__global__ __launch_bounds__(256) void k2_kernel(const float* __restrict__ hist,
                                                 const float* __restrict__ codes,
                                                 const int* __restrict__ numInt) {
    const int b = blockIdx.x;
    const int tid = threadIdx.x;
    const int w = tid >> 5;      // warp = c-chunk
    const int lane = tid & 31;   // lane = k

    __shared__ __align__(16) float row_sm[8 * 256];
    __shared__ float partial_sm[8][8][32];
    __shared__ float scores_sm[32][100];
    __shared__ __align__(16) float attnT_sm[100][32];

    // context-code chunk (this warp's 32 c's for k=lane) as 16 packed pairs
    u64 creg2[16];
    {
        const u64* cbase = (const u64*)(codes + (size_t)lane * 256 + w * 32);
#pragma unroll
        for (int j = 0; j < 16; j++) creg2[j] = cbase[j];
    }

    const float* Pb = g_proj + (size_t)b * LEN * DIM;

    for (int l0 = 0; l0 < LEN; l0 += 8) {
        const int nr = (LEN - l0 >= 8) ? 8 : (LEN - l0);
        // rows l0..l0+nr-1 are contiguous: vectorized copy
        const float4* src = (const float4*)(Pb + (size_t)l0 * DIM);
        float4* dst = (float4*)row_sm;
        const int tot = nr * 64;
        if (tid < tot) dst[tid] = src[tid];
        if (tid + 256 < tot) dst[tid + 256] = src[tid + 256];
        __syncthreads();

        u64 p[8];
#pragma unroll
        for (int r = 0; r < 8; r++) p[r] = 0ull;

        const u64* rbase = (const u64*)row_sm;   // row r: offset r*128 u64
#pragma unroll
        for (int j2 = 0; j2 < 16; j2++) {
            const u64 c = creg2[j2];
            const int coff = w * 16 + j2;
#pragma unroll
            for (int r = 0; r < 8; r++)
                p[r] = ffma2(c, rbase[r * 128 + coff], p[r]);
        }
#pragma unroll
        for (int r = 0; r < 8; r++) {
            float2 t = unpack2(p[r]);
            partial_sm[w][r][lane] = t.x + t.y;
        }
        __syncthreads();

        {
            const int k = tid & 31, r = tid >> 5;
            float s = 0.f;
#pragma unroll
            for (int ww = 0; ww < 8; ww++) s += partial_sm[ww][r][k];
            if (l0 + r < LEN) scores_sm[k][l0 + r] = s;
        }
        // partial_sm reuse protected by the sync after next iteration's row load
    }
    __syncthreads();

    // softmax over L per interest code (warp per k, 4 rounds)
    const int ni = numInt[b];
    for (int k = w; k < 32; k += 8) {
        if (k >= ni) {
            for (int l = lane; l < LEN; l += 32) scores_sm[k][l] = 0.01f;
        } else {
            float m = -3.4e38f;
            for (int l = lane; l < LEN; l += 32) m = fmaxf(m, scores_sm[k][l]);
#pragma unroll
            for (int off = 16; off; off >>= 1)
                m = fmaxf(m, __shfl_xor_sync(0xffffffffu, m, off));
            float s = 0.f;
            for (int l = lane; l < LEN; l += 32) {
                float e = expf(scores_sm[k][l] - m);
                scores_sm[k][l] = e;
                s += e;
            }
#pragma unroll
            for (int off = 16; off; off >>= 1) s += __shfl_xor_sync(0xffffffffu, s, off);
            for (int l = lane; l < LEN; l += 32) scores_sm[k][l] = scores_sm[k][l] / s;
        }
    }
    __syncthreads();

    // transpose attn for packed broadcast reads
    for (int idx = tid; idx < LEN * 32; idx += 256) {
        const int l = idx >> 5, k = idx & 31;
        attnT_sm[l][k] = scores_sm[k][l];
    }
    __syncthreads();

    // interests[k, d=tid] = sum_l attn[k,l]*hist[l,tid]   (k packed pairwise)
    u64 accI[16];
#pragma unroll
    for (int j = 0; j < 16; j++) accI[j] = 0ull;

    const float* Hb = hist + (size_t)b * LEN * DIM;
    float hv = Hb[tid];
    for (int l = 0; l < LEN; l++) {
        const float hn = (l + 1 < LEN) ? Hb[(size_t)(l + 1) * 256 + tid] : 0.f;
        const u64 hvv = pack2(hv, hv);
        const u64* arow = (const u64*)&attnT_sm[l][0];
#pragma unroll
        for (int j = 0; j < 16; j++) accI[j] = ffma2(hvv, arow[j], accI[j]);
        hv = hn;
    }
    float* Ib = g_inter + (size_t)b * KIN * DIM;
#pragma unroll
    for (int j = 0; j < 16; j++) {
        float2 t = unpack2(accI[j]);
        Ib[(size_t)(2 * j) * 256 + tid]     = t.x;
        Ib[(size_t)(2 * j + 1) * 256 + tid] = t.y;
    }
}

// ---------------------------------------------------------------------------
// K4: per-batch  w = cand·interests^T -> dynK top-k mask -> user = (w*mask)·interests
// 8 candidate rows per iteration, packed f32x2.
// ---------------------------------------------------------------------------
__global__ __launch_bounds__(256) void k4_kernel(const float* __restrict__ cand,
                                                 const int* __restrict__ catCnt,
                                                 float* __restrict__ out) {
    const int b = blockIdx.x;
    const int tid = threadIdx.x;
    const int w = tid >> 5;
    const int lane = tid & 31;

    __shared__ __align__(16) float inter_sm[32 * 256];
    __shared__ __align__(16) float row_sm[8 * 256];
    __shared__ float partial_sm[8][8][32];
    __shared__ float wfull_sm[8][32];
    __shared__ __align__(16) float wmask_sm[32][64];

    const float* Ib = g_inter + (size_t)b * KIN * DIM;
    {
        const float4* src = (const float4*)Ib;
        float4* dst = (float4*)inter_sm;
#pragma unroll
        for (int t = 0; t < 8; t++) dst[tid + t * 256] = src[tid + t * 256];
    }
    __syncthreads();

    u64 ireg2[16];
    {
        const u64* ibase = (const u64*)&inter_sm[lane * 256 + w * 32];
#pragma unroll
        for (int j = 0; j < 16; j++) ireg2[j] = ibase[j];
    }

    const int cc = catCnt[b];
    int dynK = (int)ceilf(log2f(8.0f * (float)cc));
    dynK = dynK < 1 ? 1 : (dynK > 32 ? 32 : dynK);

    const float* Cb = cand + (size_t)b * NCAND * DIM;
    for (int n0 = 0; n0 < NCAND; n0 += 8) {
        const float4* src = (const float4*)(Cb + (size_t)n0 * DIM);
        float4* dst = (float4*)row_sm;
        dst[tid] = src[tid];
        dst[tid + 256] = src[tid + 256];
        __syncthreads();

        u64 p[8];
#pragma unroll
        for (int r = 0; r < 8; r++) p[r] = 0ull;
        const u64* rbase = (const u64*)row_sm;
#pragma unroll
        for (int j2 = 0; j2 < 16; j2++) {
            const u64 iv = ireg2[j2];
            const int coff = w * 16 + j2;
#pragma unroll
            for (int r = 0; r < 8; r++)
                p[r] = ffma2(iv, rbase[r * 128 + coff], p[r]);
        }
#pragma unroll
        for (int r = 0; r < 8; r++) {
            float2 t = unpack2(p[r]);
            partial_sm[w][r][lane] = t.x + t.y;
        }
        __syncthreads();

        {
            const int k = tid & 31, r = tid >> 5;
            float s = 0.f;
#pragma unroll
            for (int ww = 0; ww < 8; ww++) s += partial_sm[ww][r][k];
            wfull_sm[r][k] = s;
        }
        __syncthreads();

        // rank: warp w handles candidate row n0+w (lane = k)
        {
            const float wi = wfull_sm[w][lane];
            int rank = 0;
#pragma unroll
            for (int j = 0; j < 32; j++) {
                const float wj = __shfl_sync(0xffffffffu, wi, j);
                rank += (wj > wi) || (wj == wi && j < lane);
            }
            wmask_sm[lane][n0 + w] = (rank < dynK) ? wi : 0.f;
        }
        // wfull/partial reuse protected by syncs in the next iteration
    }
    __syncthreads();

    // user[n, d=tid] = sum_k wmask[n,k] * interests[k,tid]   (n packed pairwise)
    u64 accU[32];
#pragma unroll
    for (int j = 0; j < 32; j++) accU[j] = 0ull;

#pragma unroll
    for (int k = 0; k < 32; k++) {
        const float iv = inter_sm[k * 256 + tid];
        const u64 ivv = pack2(iv, iv);
        const u64* wrow = (const u64*)&wmask_sm[k][0];
#pragma unroll
        for (int j = 0; j < 32; j++) accU[j] = ffma2(ivv, wrow[j], accU[j]);
    }

    float* Ob = out + (size_t)b * NCAND * DIM;
#pragma unroll
    for (int j = 0; j < 32; j++) {
        float2 t = unpack2(accU[j]);
        Ob[(size_t)(2 * j) * 256 + tid]     = t.x;
        Ob[(size_t)(2 * j + 1) * 256 + tid] = t.y;
    }
}

// ---------------------------------------------------------------------------
extern "C" void kernel_launch(void* const* d_in, const int* in_sizes, int n_in,
                              void* d_out, int out_size) {
    (void)in_sizes; (void)n_in; (void)out_size;
    const float* hist  = (const float*)d_in[0];
    const float* cand  = (const float*)d_in[2];
    const int*   numI  = (const int*)d_in[3];
    const int*   catC  = (const int*)d_in[4];
    const float* W     = (const float*)d_in[5];
    const float* codes = (const float*)d_in[6];
    float* out = (float*)d_out;

    k1_proj_kernel<<<dim3(2, 400), 256>>>(hist, W);
    k2_kernel<<<BSZ, 256>>>(hist, codes, numI);
    k4_kernel<<<BSZ, 256>>>(cand, catC, out);
}

// round 4
// speedup vs baseline: 1.3808x; 1.1766x over previous
#include <cuda_runtime.h>
#include <cuda_bf16.h>
#include <math.h>
#include <stdint.h>

#define BSZ   512
#define LEN   100
#define NCAND 64
#define DIM   256
#define KIN   32

typedef unsigned long long u64;

// Scratch (no allocations allowed)
__device__ float g_proj[BSZ * LEN * DIM];
__device__ float g_inter[BSZ * KIN * DIM];
__device__ __nv_bfloat16 g_w1[256 * 256];
__device__ __nv_bfloat16 g_w2[256 * 256];
__device__ __nv_bfloat16 g_w3[256 * 256];

// ---- packed fp32x2 helpers ------------------------------------------------
__device__ __forceinline__ u64 ffma2(u64 a, u64 b, u64 c) {
    u64 d;
    asm("fma.rn.f32x2 %0, %1, %2, %3;" : "=l"(d) : "l"(a), "l"(b), "l"(c));
    return d;
}
__device__ __forceinline__ u64 pack2(float lo, float hi) {
    u64 r;
    asm("mov.b64 %0, {%1, %2};" : "=l"(r) : "f"(lo), "f"(hi));
    return r;
}
__device__ __forceinline__ float2 unpack2(u64 v) {
    float2 r;
    asm("mov.b64 {%0, %1}, %2;" : "=f"(r.x), "=f"(r.y) : "l"(v));
    return r;
}

// ---- mma.sync helpers (baseline PTX, works on compute_103) -----------------
__device__ __forceinline__ uint32_t smem_u32(const void* p) {
    uint32_t a;
    asm("{ .reg .u64 t; cvta.to.shared.u64 t, %1; cvt.u32.u64 %0, t; }" : "=r"(a) : "l"(p));
    return a;
}
__device__ __forceinline__ void ldsm4(uint32_t* r, uint32_t addr) {
    asm volatile("ldmatrix.sync.aligned.m8n8.x4.shared.b16 {%0,%1,%2,%3}, [%4];"
                 : "=r"(r[0]), "=r"(r[1]), "=r"(r[2]), "=r"(r[3]) : "r"(addr) : "memory");
}
__device__ __forceinline__ void mma16816(float* d, const uint32_t* a, uint32_t b0, uint32_t b1) {
    asm volatile("mma.sync.aligned.m16n8k16.row.col.f32.bf16.bf16.f32 "
                 "{%0,%1,%2,%3}, {%4,%5,%6,%7}, {%8,%9}, {%0,%1,%2,%3};"
                 : "+f"(d[0]), "+f"(d[1]), "+f"(d[2]), "+f"(d[3])
                 : "r"(a[0]), "r"(a[1]), "r"(a[2]), "r"(a[3]), "r"(b0), "r"(b1));
}

#define SWZ(o) ((o) ^ (((o) >> 3) & 0x70))

__device__ __forceinline__ uint32_t bf2_u32(__nv_bfloat16 a, __nv_bfloat16 b) {
    __nv_bfloat162 t(a, b);
    return *reinterpret_cast<uint32_t*>(&t);
}

// SMEM layout (per CTA, single buffer): A1|A2|A3|B1|B2|B3, 16KB each = 96KB
#define A_OFF  0
#define B_OFF  49152
#define LVL    16384
#define K1_SMEM (98304 + 1024)

// ---------------------------------------------------------------------------
// W split: W (fp32) -> 3 bf16 levels
// ---------------------------------------------------------------------------
__global__ void kw_split(const float* __restrict__ W) {
    const int i = blockIdx.x * 256 + threadIdx.x;
    const float a = W[i];
    const __nv_bfloat16 h1 = __float2bfloat16(a);
    const float r1 = a - __bfloat162float(h1);
    const __nv_bfloat16 h2 = __float2bfloat16(r1);
    const float r2 = r1 - __bfloat162float(h2);
    g_w1[i] = h1;
    g_w2[i] = h2;
    g_w3[i] = __float2bfloat16(r2);
}

// ---------------------------------------------------------------------------
// K1: proj = tanh(hist @ W^T) via mma.sync bf16, 3-level split (6 passes).
// CTA tile 128x128, 8 warps (warp tile 64x32), K chunked x64.
// ---------------------------------------------------------------------------
__global__ void __launch_bounds__(256, 2) k1_mma(const float* __restrict__ hist) {
    extern __shared__ char smem_raw[];
    const int tid = threadIdx.x;
    const int wid = tid >> 5;
    const int lane = tid & 31;
    const int warp_m = wid >> 2;         // 0..1
    const int warp_n = wid & 3;          // 0..3
    const int m0 = blockIdx.y * 128;
    const int n0 = blockIdx.x * 128;

    const uint32_t sb_raw = smem_u32(smem_raw);
    const uint32_t sb = (sb_raw + 1023u) & ~1023u;
    char* smem = smem_raw + (sb - sb_raw);

    const int g  = lane >> 3;            // ldmatrix address group 0..3
    const int rw = lane & 7;

    float acc[4][4][4];
#pragma unroll
    for (int mt = 0; mt < 4; mt++)
#pragma unroll
        for (int nt = 0; nt < 4; nt++)
#pragma unroll
            for (int i = 0; i < 4; i++) acc[mt][nt][i] = 0.f;

    for (int kc = 0; kc < 4; kc++) {
        // ---- load + 3-split A chunk: 128 rows x 64 fp32
#pragma unroll
        for (int t = 0; t < 8; t++) {
            const int idx = tid + t * 256;
            const int r = idx >> 4, c4 = idx & 15;
            const float4 a = __ldg((const float4*)&hist[(size_t)(m0 + r) * 256 + kc * 64 + c4 * 4]);
            const __nv_bfloat16 h1x = __float2bfloat16(a.x), h1y = __float2bfloat16(a.y);
            const __nv_bfloat16 h1z = __float2bfloat16(a.z), h1w = __float2bfloat16(a.w);
            const float r1x = a.x - __bfloat162float(h1x), r1y = a.y - __bfloat162float(h1y);
            const float r1z = a.z - __bfloat162float(h1z), r1w = a.w - __bfloat162float(h1w);
            const __nv_bfloat16 h2x = __float2bfloat16(r1x), h2y = __float2bfloat16(r1y);
            const __nv_bfloat16 h2z = __float2bfloat16(r1z), h2w = __float2bfloat16(r1w);
            const __nv_bfloat16 h3x = __float2bfloat16(r1x - __bfloat162float(h2x));
            const __nv_bfloat16 h3y = __float2bfloat16(r1y - __bfloat162float(h2y));
            const __nv_bfloat16 h3z = __float2bfloat16(r1z - __bfloat162float(h2z));
            const __nv_bfloat16 h3w = __float2bfloat16(r1w - __bfloat162float(h2w));
            const uint32_t off = SWZ((uint32_t)(r * 128 + c4 * 8));
            *(uint2*)(smem + A_OFF + 0 * LVL + off) = make_uint2(bf2_u32(h1x, h1y), bf2_u32(h1z, h1w));
            *(uint2*)(smem + A_OFF + 1 * LVL + off) = make_uint2(bf2_u32(h2x, h2y), bf2_u32(h2z, h2w));
            *(uint2*)(smem + A_OFF + 2 * LVL + off) = make_uint2(bf2_u32(h3x, h3y), bf2_u32(h3z, h3w));
        }
        // ---- load B chunk (pre-split): 128 n-rows x 64 k, 3 levels
        {
            const __nv_bfloat16* gw[3] = {g_w1, g_w2, g_w3};
#pragma unroll
            for (int lv = 0; lv < 3; lv++) {
#pragma unroll
                for (int t = 0; t < 4; t++) {
                    const int idx = tid + t * 256;
                    const int n = idx >> 3, u = idx & 7;
                    const uint4 v = *(const uint4*)&gw[lv][(size_t)(n0 + n) * 256 + kc * 64 + u * 8];
                    *(uint4*)(smem + B_OFF + lv * LVL + SWZ((uint32_t)(n * 128 + u * 16))) = v;
                }
            }
        }
        __syncthreads();

        // ---- compute 4 k-steps of 16
#pragma unroll
        for (int ks = 0; ks < 4; ks++) {
            const int k0 = ks * 16;
            uint32_t aoff[4], boff[2];
#pragma unroll
            for (int mt = 0; mt < 4; mt++) {
                const int row = warp_m * 64 + mt * 16 + ((g & 1) << 3) + rw;
                const int kk  = k0 + ((g >> 1) << 3);
                aoff[mt] = sb + A_OFF + SWZ((uint32_t)(row * 128 + kk * 2));
            }
#pragma unroll
            for (int nt2 = 0; nt2 < 2; nt2++) {
                const int row = warp_n * 32 + nt2 * 16 + ((g >> 1) << 3) + rw;
                const int kk  = k0 + ((g & 1) << 3);
                boff[nt2] = sb + B_OFF + SWZ((uint32_t)(row * 128 + kk * 2));
            }
#pragma unroll
            for (int la = 0; la < 3; la++) {
                uint32_t af[4][4];
#pragma unroll
                for (int mt = 0; mt < 4; mt++) ldsm4(af[mt], aoff[mt] + la * LVL);
#pragma unroll
                for (int lb = 0; lb < 3; lb++) {
                    if (la + lb > 2) break;
                    uint32_t bf[2][4];
#pragma unroll
                    for (int nt2 = 0; nt2 < 2; nt2++) ldsm4(bf[nt2], boff[nt2] + lb * LVL);
#pragma unroll
                    for (int mt = 0; mt < 4; mt++) {
#pragma unroll
                        for (int nt = 0; nt < 4; nt++)
                            mma16816(acc[mt][nt], af[mt],
                                     bf[nt >> 1][(nt & 1) * 2], bf[nt >> 1][(nt & 1) * 2 + 1]);
                    }
                }
            }
        }
        __syncthreads();
    }

    // ---- epilogue: tanh + store
    const int gid = lane >> 2, tig = lane & 3;
#pragma unroll
    for (int mt = 0; mt < 4; mt++) {
#pragma unroll
        for (int nt = 0; nt < 4; nt++) {
            const int row = m0 + warp_m * 64 + mt * 16 + gid;
            const int col = n0 + warp_n * 32 + nt * 8 + tig * 2;
            float2 v0, v1;
            v0.x = tanhf(acc[mt][nt][0]); v0.y = tanhf(acc[mt][nt][1]);
            v1.x = tanhf(acc[mt][nt][2]); v1.y = tanhf(acc[mt][nt][3]);
            *(float2*)&g_proj[(size_t)row * 256 + col]       = v0;
            *(float2*)&g_proj[(size_t)(row + 8) * 256 + col] = v1;
        }
    }
}

// ---------------------------------------------------------------------------
// K2: per-batch  scores -> mask -> softmax(L) -> interests   (unchanged)
// ---------------------------------------------------------------------------
__global__ __launch_bounds__(256) void k2_kernel(const float* __restrict__ hist,
                                                 const float* __restrict__ codes,
                                                 const int* __restrict__ numInt) {
    const int b = blockIdx.x;
    const int tid = threadIdx.x;
    const int w = tid >> 5;
    const int lane = tid & 31;

    __shared__ __align__(16) float row_sm[8 * 256];
    __shared__ float partial_sm[8][8][32];
    __shared__ float scores_sm[32][100];
    __shared__ __align__(16) float attnT_sm[100][32];

    u64 creg2[16];
    {
        const u64* cbase = (const u64*)(codes + (size_t)lane * 256 + w * 32);
#pragma unroll
        for (int j = 0; j < 16; j++) creg2[j] = cbase[j];
    }

    const float* Pb = g_proj + (size_t)b * LEN * DIM;

    for (int l0 = 0; l0 < LEN; l0 += 8) {
        const int nr = (LEN - l0 >= 8) ? 8 : (LEN - l0);
        const float4* src = (const float4*)(Pb + (size_t)l0 * DIM);
        float4* dst = (float4*)row_sm;
        const int tot = nr * 64;
        if (tid < tot) dst[tid] = src[tid];
        if (tid + 256 < tot) dst[tid + 256] = src[tid + 256];
        __syncthreads();

        u64 p[8];
#pragma unroll
        for (int r = 0; r < 8; r++) p[r] = 0ull;

        const u64* rbase = (const u64*)row_sm;
#pragma unroll
        for (int j2 = 0; j2 < 16; j2++) {
            const u64 c = creg2[j2];
            const int coff = w * 16 + j2;
#pragma unroll
            for (int r = 0; r < 8; r++)
                p[r] = ffma2(c, rbase[r * 128 + coff], p[r]);
        }
#pragma unroll
        for (int r = 0; r < 8; r++) {
            float2 t = unpack2(p[r]);
            partial_sm[w][r][lane] = t.x + t.y;
        }
        __syncthreads();

        {
            const int k = tid & 31, r = tid >> 5;
            float s = 0.f;
#pragma unroll
            for (int ww = 0; ww < 8; ww++) s += partial_sm[ww][r][k];
            if (l0 + r < LEN) scores_sm[k][l0 + r] = s;
        }
    }
    __syncthreads();

    const int ni = numInt[b];
    for (int k = w; k < 32; k += 8) {
        if (k >= ni) {
            for (int l = lane; l < LEN; l += 32) scores_sm[k][l] = 0.01f;
        } else {
            float m = -3.4e38f;
            for (int l = lane; l < LEN; l += 32) m = fmaxf(m, scores_sm[k][l]);
#pragma unroll
            for (int off = 16; off; off >>= 1)
                m = fmaxf(m, __shfl_xor_sync(0xffffffffu, m, off));
            float s = 0.f;
            for (int l = lane; l < LEN; l += 32) {
                float e = expf(scores_sm[k][l] - m);
                scores_sm[k][l] = e;
                s += e;
            }
#pragma unroll
            for (int off = 16; off; off >>= 1) s += __shfl_xor_sync(0xffffffffu, s, off);
            for (int l = lane; l < LEN; l += 32) scores_sm[k][l] = scores_sm[k][l] / s;
        }
    }
    __syncthreads();

    for (int idx = tid; idx < LEN * 32; idx += 256) {
        const int l = idx >> 5, k = idx & 31;
        attnT_sm[l][k] = scores_sm[k][l];
    }
    __syncthreads();

    u64 accI[16];
#pragma unroll
    for (int j = 0; j < 16; j++) accI[j] = 0ull;

    const float* Hb = hist + (size_t)b * LEN * DIM;
    float hv = Hb[tid];
    for (int l = 0; l < LEN; l++) {
        const float hn = (l + 1 < LEN) ? Hb[(size_t)(l + 1) * 256 + tid] : 0.f;
        const u64 hvv = pack2(hv, hv);
        const u64* arow = (const u64*)&attnT_sm[l][0];
#pragma unroll
        for (int j = 0; j < 16; j++) accI[j] = ffma2(hvv, arow[j], accI[j]);
        hv = hn;
    }
    float* Ib = g_inter + (size_t)b * KIN * DIM;
#pragma unroll
    for (int j = 0; j < 16; j++) {
        float2 t = unpack2(accI[j]);
        Ib[(size_t)(2 * j) * 256 + tid]     = t.x;
        Ib[(size_t)(2 * j + 1) * 256 + tid] = t.y;
    }
}

// ---------------------------------------------------------------------------
// K4: per-batch  w -> dynK top-k mask -> user   (unchanged)
// ---------------------------------------------------------------------------
__global__ __launch_bounds__(256) void k4_kernel(const float* __restrict__ cand,
                                                 const int* __restrict__ catCnt,
                                                 float* __restrict__ out) {
    const int b = blockIdx.x;
    const int tid = threadIdx.x;
    const int w = tid >> 5;
    const int lane = tid & 31;

    __shared__ __align__(16) float inter_sm[32 * 256];
    __shared__ __align__(16) float row_sm[8 * 256];
    __shared__ float partial_sm[8][8][32];
    __shared__ float wfull_sm[8][32];
    __shared__ __align__(16) float wmask_sm[32][64];

    const float* Ib = g_inter + (size_t)b * KIN * DIM;
    {
        const float4* src = (const float4*)Ib;
        float4* dst = (float4*)inter_sm;
#pragma unroll
        for (int t = 0; t < 8; t++) dst[tid + t * 256] = src[tid + t * 256];
    }
    __syncthreads();

    u64 ireg2[16];
    {
        const u64* ibase = (const u64*)&inter_sm[lane * 256 + w * 32];
#pragma unroll
        for (int j = 0; j < 16; j++) ireg2[j] = ibase[j];
    }

    const int cc = catCnt[b];
    int dynK = (int)ceilf(log2f(8.0f * (float)cc));
    dynK = dynK < 1 ? 1 : (dynK > 32 ? 32 : dynK);

    const float* Cb = cand + (size_t)b * NCAND * DIM;
    for (int n0 = 0; n0 < NCAND; n0 += 8) {
        const float4* src = (const float4*)(Cb + (size_t)n0 * DIM);
        float4* dst = (float4*)row_sm;
        dst[tid] = src[tid];
        dst[tid + 256] = src[tid + 256];
        __syncthreads();

        u64 p[8];
#pragma unroll
        for (int r = 0; r < 8; r++) p[r] = 0ull;
        const u64* rbase = (const u64*)row_sm;
#pragma unroll
        for (int j2 = 0; j2 < 16; j2++) {
            const u64 iv = ireg2[j2];
            const int coff = w * 16 + j2;
#pragma unroll
            for (int r = 0; r < 8; r++)
                p[r] = ffma2(iv, rbase[r * 128 + coff], p[r]);
        }
#pragma unroll
        for (int r = 0; r < 8; r++) {
            float2 t = unpack2(p[r]);
            partial_sm[w][r][lane] = t.x + t.y;
        }
        __syncthreads();

        {
            const int k = tid & 31, r = tid >> 5;
            float s = 0.f;
#pragma unroll
            for (int ww = 0; ww < 8; ww++) s += partial_sm[ww][r][k];
            wfull_sm[r][k] = s;
        }
        __syncthreads();

        {
            const float wi = wfull_sm[w][lane];
            int rank = 0;
#pragma unroll
            for (int j = 0; j < 32; j++) {
                const float wj = __shfl_sync(0xffffffffu, wi, j);
                rank += (wj > wi) || (wj == wi && j < lane);
            }
            wmask_sm[lane][n0 + w] = (rank < dynK) ? wi : 0.f;
        }
        __syncthreads();
    }

    u64 accU[32];
#pragma unroll
    for (int j = 0; j < 32; j++) accU[j] = 0ull;

#pragma unroll
    for (int k = 0; k < 32; k++) {
        const float iv = inter_sm[k * 256 + tid];
        const u64 ivv = pack2(iv, iv);
        const u64* wrow = (const u64*)&wmask_sm[k][0];
#pragma unroll
        for (int j = 0; j < 32; j++) accU[j] = ffma2(ivv, wrow[j], accU[j]);
    }

    float* Ob = out + (size_t)b * NCAND * DIM;
#pragma unroll
    for (int j = 0; j < 32; j++) {
        float2 t = unpack2(accU[j]);
        Ob[(size_t)(2 * j) * 256 + tid]     = t.x;
        Ob[(size_t)(2 * j + 1) * 256 + tid] = t.y;
    }
}

// ---------------------------------------------------------------------------
extern "C" void kernel_launch(void* const* d_in, const int* in_sizes, int n_in,
                              void* d_out, int out_size) {
    (void)in_sizes; (void)n_in; (void)out_size;
    const float* hist  = (const float*)d_in[0];
    const float* cand  = (const float*)d_in[2];
    const int*   numI  = (const int*)d_in[3];
    const int*   catC  = (const int*)d_in[4];
    const float* W     = (const float*)d_in[5];
    const float* codes = (const float*)d_in[6];
    float* out = (float*)d_out;

    static bool attr_set = false;
    if (!attr_set) {
        cudaFuncSetAttribute(k1_mma, cudaFuncAttributeMaxDynamicSharedMemorySize, K1_SMEM);
        attr_set = true;
    }

    kw_split<<<256, 256>>>(W);
    k1_mma<<<dim3(2, 400), 256, K1_SMEM>>>(hist);
    k2_kernel<<<BSZ, 256>>>(hist, codes, numI);
    k4_kernel<<<BSZ, 256>>>(cand, catC, out);
}

// round 5
// speedup vs baseline: 1.7103x; 1.2387x over previous
#include <cuda_runtime.h>
#include <cuda_fp16.h>
#include <math.h>
#include <stdint.h>

#define BSZ   512
#define LEN   100
#define NCAND 64
#define DIM   256
#define KIN   32

typedef unsigned long long u64;

// Scratch (no allocations allowed)
__device__ float g_proj[BSZ * LEN * DIM];
__device__ float g_inter[BSZ * KIN * DIM];
__device__ __half g_h1[256 * 256];
__device__ __half g_h2[256 * 256];

// ---- packed fp32x2 helpers ------------------------------------------------
__device__ __forceinline__ u64 ffma2(u64 a, u64 b, u64 c) {
    u64 d;
    asm("fma.rn.f32x2 %0, %1, %2, %3;" : "=l"(d) : "l"(a), "l"(b), "l"(c));
    return d;
}
__device__ __forceinline__ u64 pack2(float lo, float hi) {
    u64 r;
    asm("mov.b64 %0, {%1, %2};" : "=l"(r) : "f"(lo), "f"(hi));
    return r;
}
__device__ __forceinline__ float2 unpack2(u64 v) {
    float2 r;
    asm("mov.b64 {%0, %1}, %2;" : "=f"(r.x), "=f"(r.y) : "l"(v));
    return r;
}

// ---- mma.sync helpers -------------------------------------------------------
__device__ __forceinline__ uint32_t smem_u32(const void* p) {
    uint32_t a;
    asm("{ .reg .u64 t; cvta.to.shared.u64 t, %1; cvt.u32.u64 %0, t; }" : "=r"(a) : "l"(p));
    return a;
}
__device__ __forceinline__ void ldsm4(uint32_t* r, uint32_t addr) {
    asm volatile("ldmatrix.sync.aligned.m8n8.x4.shared.b16 {%0,%1,%2,%3}, [%4];"
                 : "=r"(r[0]), "=r"(r[1]), "=r"(r[2]), "=r"(r[3]) : "r"(addr) : "memory");
}
__device__ __forceinline__ void mma16816(float* d, const uint32_t* a, uint32_t b0, uint32_t b1) {
    asm volatile("mma.sync.aligned.m16n8k16.row.col.f32.f16.f16.f32 "
                 "{%0,%1,%2,%3}, {%4,%5,%6,%7}, {%8,%9}, {%0,%1,%2,%3};"
                 : "+f"(d[0]), "+f"(d[1]), "+f"(d[2]), "+f"(d[3])
                 : "r"(a[0]), "r"(a[1]), "r"(a[2]), "r"(a[3]), "r"(b0), "r"(b1));
}

#define SWZ(o) ((o) ^ (((o) >> 3) & 0x70))

__device__ __forceinline__ uint32_t h2_u32(__half a, __half b) {
    __half2 t(a, b);
    return *reinterpret_cast<uint32_t*>(&t);
}

// SMEM layout (per CTA): A1|A2|B1|B2, 16KB each = 64KB
#define A_OFF  0
#define B_OFF  32768
#define LVL    16384
#define K1_SMEM (65536 + 1024)

// ---------------------------------------------------------------------------
// W split: W (fp32) -> 2 fp16 levels
// ---------------------------------------------------------------------------
__global__ void kw_split(const float* __restrict__ W) {
    const int i = blockIdx.x * 256 + threadIdx.x;
    const float a = W[i];
    const __half h1 = __float2half_rn(a);
    g_h1[i] = h1;
    g_h2[i] = __float2half_rn(a - __half2float(h1));
}

// ---------------------------------------------------------------------------
// K1: proj = tanh(hist @ W^T) via mma.sync fp16, 2-level split (3 passes).
// CTA tile 128x128, 8 warps (warp tile 64x32), K chunked x64.
// ---------------------------------------------------------------------------
__global__ void __launch_bounds__(256, 2) k1_mma(const float* __restrict__ hist) {
    extern __shared__ char smem_raw[];
    const int tid = threadIdx.x;
    const int wid = tid >> 5;
    const int lane = tid & 31;
    const int warp_m = wid >> 2;         // 0..1
    const int warp_n = wid & 3;          // 0..3
    const int m0 = blockIdx.y * 128;
    const int n0 = blockIdx.x * 128;

    const uint32_t sb_raw = smem_u32(smem_raw);
    const uint32_t sb = (sb_raw + 1023u) & ~1023u;
    char* smem = smem_raw + (sb - sb_raw);

    const int g  = lane >> 3;            // ldmatrix address group 0..3
    const int rw = lane & 7;

    float acc[4][4][4];
#pragma unroll
    for (int mt = 0; mt < 4; mt++)
#pragma unroll
        for (int nt = 0; nt < 4; nt++)
#pragma unroll
            for (int i = 0; i < 4; i++) acc[mt][nt][i] = 0.f;

    for (int kc = 0; kc < 4; kc++) {
        // ---- load + 2-split A chunk: 128 rows x 64 fp32 -> fp16 h1/h2
#pragma unroll
        for (int t = 0; t < 8; t++) {
            const int idx = tid + t * 256;
            const int r = idx >> 4, c4 = idx & 15;
            const float4 a = __ldg((const float4*)&hist[(size_t)(m0 + r) * 256 + kc * 64 + c4 * 4]);
            const __half h1x = __float2half_rn(a.x), h1y = __float2half_rn(a.y);
            const __half h1z = __float2half_rn(a.z), h1w = __float2half_rn(a.w);
            const __half h2x = __float2half_rn(a.x - __half2float(h1x));
            const __half h2y = __float2half_rn(a.y - __half2float(h1y));
            const __half h2z = __float2half_rn(a.z - __half2float(h1z));
            const __half h2w = __float2half_rn(a.w - __half2float(h1w));
            const uint32_t off = SWZ((uint32_t)(r * 128 + c4 * 8));
            *(uint2*)(smem + A_OFF + 0 * LVL + off) = make_uint2(h2_u32(h1x, h1y), h2_u32(h1z, h1w));
            *(uint2*)(smem + A_OFF + 1 * LVL + off) = make_uint2(h2_u32(h2x, h2y), h2_u32(h2z, h2w));
        }
        // ---- load B chunk (pre-split): 128 n-rows x 64 k, 2 levels
        {
            const __half* gw[2] = {g_h1, g_h2};
#pragma unroll
            for (int lv = 0; lv < 2; lv++) {
#pragma unroll
                for (int t = 0; t < 4; t++) {
                    const int idx = tid + t * 256;
                    const int n = idx >> 3, u = idx & 7;
                    const uint4 v = *(const uint4*)&gw[lv][(size_t)(n0 + n) * 256 + kc * 64 + u * 8];
                    *(uint4*)(smem + B_OFF + lv * LVL + SWZ((uint32_t)(n * 128 + u * 16))) = v;
                }
            }
        }
        __syncthreads();

        // ---- compute 4 k-steps of 16
#pragma unroll
        for (int ks = 0; ks < 4; ks++) {
            const int k0 = ks * 16;
            uint32_t aoff[4], boff[2];
#pragma unroll
            for (int mt = 0; mt < 4; mt++) {
                const int row = warp_m * 64 + mt * 16 + ((g & 1) << 3) + rw;
                const int kk  = k0 + ((g >> 1) << 3);
                aoff[mt] = sb + A_OFF + SWZ((uint32_t)(row * 128 + kk * 2));
            }
#pragma unroll
            for (int nt2 = 0; nt2 < 2; nt2++) {
                const int row = warp_n * 32 + nt2 * 16 + ((g >> 1) << 3) + rw;
                const int kk  = k0 + ((g & 1) << 3);
                boff[nt2] = sb + B_OFF + SWZ((uint32_t)(row * 128 + kk * 2));
            }

            uint32_t a0[4][4], a1[4][4], b0[2][4], b1[2][4];
#pragma unroll
            for (int mt = 0; mt < 4; mt++) { ldsm4(a0[mt], aoff[mt]); ldsm4(a1[mt], aoff[mt] + LVL); }
#pragma unroll
            for (int nt2 = 0; nt2 < 2; nt2++) { ldsm4(b0[nt2], boff[nt2]); ldsm4(b1[nt2], boff[nt2] + LVL); }

#pragma unroll
            for (int mt = 0; mt < 4; mt++)
#pragma unroll
                for (int nt = 0; nt < 4; nt++) {
                    const int h = nt >> 1, q = (nt & 1) * 2;
                    mma16816(acc[mt][nt], a0[mt], b0[h][q], b0[h][q + 1]);   // h1*w1
                    mma16816(acc[mt][nt], a0[mt], b1[h][q], b1[h][q + 1]);   // h1*w2
                    mma16816(acc[mt][nt], a1[mt], b0[h][q], b0[h][q + 1]);   // h2*w1
                }
        }
        __syncthreads();
    }

    // ---- epilogue: tanh + store
    const int gid = lane >> 2, tig = lane & 3;
#pragma unroll
    for (int mt = 0; mt < 4; mt++) {
#pragma unroll
        for (int nt = 0; nt < 4; nt++) {
            const int row = m0 + warp_m * 64 + mt * 16 + gid;
            const int col = n0 + warp_n * 32 + nt * 8 + tig * 2;
            float2 v0, v1;
            v0.x = tanhf(acc[mt][nt][0]); v0.y = tanhf(acc[mt][nt][1]);
            v1.x = tanhf(acc[mt][nt][2]); v1.y = tanhf(acc[mt][nt][3]);
            *(float2*)&g_proj[(size_t)row * 256 + col]       = v0;
            *(float2*)&g_proj[(size_t)(row + 8) * 256 + col] = v1;
        }
    }
}

// ---------------------------------------------------------------------------
// K2: per-batch  scores -> mask -> softmax(L) -> interests
// (interests phase now 4-deep prefetched)
// ---------------------------------------------------------------------------
__global__ __launch_bounds__(256) void k2_kernel(const float* __restrict__ hist,
                                                 const float* __restrict__ codes,
                                                 const int* __restrict__ numInt) {
    const int b = blockIdx.x;
    const int tid = threadIdx.x;
    const int w = tid >> 5;
    const int lane = tid & 31;

    __shared__ __align__(16) float row_sm[8 * 256];
    __shared__ float partial_sm[8][8][32];
    __shared__ float scores_sm[32][100];
    __shared__ __align__(16) float attnT_sm[100][32];

    u64 creg2[16];
    {
        const u64* cbase = (const u64*)(codes + (size_t)lane * 256 + w * 32);
#pragma unroll
        for (int j = 0; j < 16; j++) creg2[j] = cbase[j];
    }

    const float* Pb = g_proj + (size_t)b * LEN * DIM;

    for (int l0 = 0; l0 < LEN; l0 += 8) {
        const int nr = (LEN - l0 >= 8) ? 8 : (LEN - l0);
        const float4* src = (const float4*)(Pb + (size_t)l0 * DIM);
        float4* dst = (float4*)row_sm;
        const int tot = nr * 64;
        if (tid < tot) dst[tid] = src[tid];
        if (tid + 256 < tot) dst[tid + 256] = src[tid + 256];
        __syncthreads();

        u64 p[8];
#pragma unroll
        for (int r = 0; r < 8; r++) p[r] = 0ull;

        const u64* rbase = (const u64*)row_sm;
#pragma unroll
        for (int j2 = 0; j2 < 16; j2++) {
            const u64 c = creg2[j2];
            const int coff = w * 16 + j2;
#pragma unroll
            for (int r = 0; r < 8; r++)
                p[r] = ffma2(c, rbase[r * 128 + coff], p[r]);
        }
#pragma unroll
        for (int r = 0; r < 8; r++) {
            float2 t = unpack2(p[r]);
            partial_sm[w][r][lane] = t.x + t.y;
        }
        __syncthreads();

        {
            const int k = tid & 31, r = tid >> 5;
            float s = 0.f;
#pragma unroll
            for (int ww = 0; ww < 8; ww++) s += partial_sm[ww][r][k];
            if (l0 + r < LEN) scores_sm[k][l0 + r] = s;
        }
    }
    __syncthreads();

    const int ni = numInt[b];
    for (int k = w; k < 32; k += 8) {
        if (k >= ni) {
            for (int l = lane; l < LEN; l += 32) scores_sm[k][l] = 0.01f;
        } else {
            float m = -3.4e38f;
            for (int l = lane; l < LEN; l += 32) m = fmaxf(m, scores_sm[k][l]);
#pragma unroll
            for (int off = 16; off; off >>= 1)
                m = fmaxf(m, __shfl_xor_sync(0xffffffffu, m, off));
            float s = 0.f;
            for (int l = lane; l < LEN; l += 32) {
                float e = expf(scores_sm[k][l] - m);
                scores_sm[k][l] = e;
                s += e;
            }
#pragma unroll
            for (int off = 16; off; off >>= 1) s += __shfl_xor_sync(0xffffffffu, s, off);
            for (int l = lane; l < LEN; l += 32) scores_sm[k][l] = scores_sm[k][l] / s;
        }
    }
    __syncthreads();

    for (int idx = tid; idx < LEN * 32; idx += 256) {
        const int l = idx >> 5, k = idx & 31;
        attnT_sm[l][k] = scores_sm[k][l];
    }
    __syncthreads();

    // interests[k, d=tid] = sum_l attn[k,l]*hist[l,tid], 4-row prefetch
    u64 accI[16];
#pragma unroll
    for (int j = 0; j < 16; j++) accI[j] = 0ull;

    const float* Hb = hist + (size_t)b * LEN * DIM;
    float hv[4];
#pragma unroll
    for (int r = 0; r < 4; r++) hv[r] = Hb[(size_t)r * 256 + tid];

    for (int l0 = 0; l0 < LEN; l0 += 4) {
        float hn[4];
        if (l0 + 4 < LEN) {
#pragma unroll
            for (int r = 0; r < 4; r++) hn[r] = Hb[(size_t)(l0 + 4 + r) * 256 + tid];
        } else {
#pragma unroll
            for (int r = 0; r < 4; r++) hn[r] = 0.f;
        }
#pragma unroll
        for (int r = 0; r < 4; r++) {
            const u64 hvv = pack2(hv[r], hv[r]);
            const u64* arow = (const u64*)&attnT_sm[l0 + r][0];
#pragma unroll
            for (int j = 0; j < 16; j++) accI[j] = ffma2(hvv, arow[j], accI[j]);
        }
#pragma unroll
        for (int r = 0; r < 4; r++) hv[r] = hn[r];
    }

    float* Ib = g_inter + (size_t)b * KIN * DIM;
#pragma unroll
    for (int j = 0; j < 16; j++) {
        float2 t = unpack2(accI[j]);
        Ib[(size_t)(2 * j) * 256 + tid]     = t.x;
        Ib[(size_t)(2 * j + 1) * 256 + tid] = t.y;
    }
}

// ---------------------------------------------------------------------------
// K4: 2 blocks per batch (32 candidates each): w -> dynK top-k mask -> user
// ---------------------------------------------------------------------------
__global__ __launch_bounds__(256) void k4_kernel(const float* __restrict__ cand,
                                                 const int* __restrict__ catCnt,
                                                 float* __restrict__ out) {
    const int b = blockIdx.x >> 1;
    const int nbase = (blockIdx.x & 1) * 32;
    const int tid = threadIdx.x;
    const int w = tid >> 5;
    const int lane = tid & 31;

    __shared__ __align__(16) float inter_sm[32 * 256];
    __shared__ __align__(16) float row_sm[8 * 256];
    __shared__ float partial_sm[8][8][32];
    __shared__ float wfull_sm[8][32];
    __shared__ __align__(16) float wmask_sm[32][32];

    const float* Ib = g_inter + (size_t)b * KIN * DIM;
    {
        const float4* src = (const float4*)Ib;
        float4* dst = (float4*)inter_sm;
#pragma unroll
        for (int t = 0; t < 8; t++) dst[tid + t * 256] = src[tid + t * 256];
    }
    __syncthreads();

    u64 ireg2[16];
    {
        const u64* ibase = (const u64*)&inter_sm[lane * 256 + w * 32];
#pragma unroll
        for (int j = 0; j < 16; j++) ireg2[j] = ibase[j];
    }

    const int cc = catCnt[b];
    int dynK = (int)ceilf(log2f(8.0f * (float)cc));
    dynK = dynK < 1 ? 1 : (dynK > 32 ? 32 : dynK);

    const float* Cb = cand + (size_t)b * NCAND * DIM + (size_t)nbase * DIM;
    for (int n0 = 0; n0 < 32; n0 += 8) {
        const float4* src = (const float4*)(Cb + (size_t)n0 * DIM);
        float4* dst = (float4*)row_sm;
        dst[tid] = src[tid];
        dst[tid + 256] = src[tid + 256];
        __syncthreads();

        u64 p[8];
#pragma unroll
        for (int r = 0; r < 8; r++) p[r] = 0ull;
        const u64* rbase = (const u64*)row_sm;
#pragma unroll
        for (int j2 = 0; j2 < 16; j2++) {
            const u64 iv = ireg2[j2];
            const int coff = w * 16 + j2;
#pragma unroll
            for (int r = 0; r < 8; r++)
                p[r] = ffma2(iv, rbase[r * 128 + coff], p[r]);
        }
#pragma unroll
        for (int r = 0; r < 8; r++) {
            float2 t = unpack2(p[r]);
            partial_sm[w][r][lane] = t.x + t.y;
        }
        __syncthreads();

        {
            const int k = tid & 31, r = tid >> 5;
            float s = 0.f;
#pragma unroll
            for (int ww = 0; ww < 8; ww++) s += partial_sm[ww][r][k];
            wfull_sm[r][k] = s;
        }
        __syncthreads();

        {
            const float wi = wfull_sm[w][lane];
            int rank = 0;
#pragma unroll
            for (int j = 0; j < 32; j++) {
                const float wj = __shfl_sync(0xffffffffu, wi, j);
                rank += (wj > wi) || (wj == wi && j < lane);
            }
            wmask_sm[lane][n0 + w] = (rank < dynK) ? wi : 0.f;
        }
        __syncthreads();
    }

    // user[n, d=tid] = sum_k wmask[n,k] * interests[k,tid]   (n packed pairwise)
    u64 accU[16];
#pragma unroll
    for (int j = 0; j < 16; j++) accU[j] = 0ull;

#pragma unroll
    for (int k = 0; k < 32; k++) {
        const float iv = inter_sm[k * 256 + tid];
        const u64 ivv = pack2(iv, iv);
        const u64* wrow = (const u64*)&wmask_sm[k][0];
#pragma unroll
        for (int j = 0; j < 16; j++) accU[j] = ffma2(ivv, wrow[j], accU[j]);
    }

    float* Ob = out + (size_t)b * NCAND * DIM + (size_t)nbase * DIM;
#pragma unroll
    for (int j = 0; j < 16; j++) {
        float2 t = unpack2(accU[j]);
        Ob[(size_t)(2 * j) * 256 + tid]     = t.x;
        Ob[(size_t)(2 * j + 1) * 256 + tid] = t.y;
    }
}

// ---------------------------------------------------------------------------
extern "C" void kernel_launch(void* const* d_in, const int* in_sizes, int n_in,
                              void* d_out, int out_size) {
    (void)in_sizes; (void)n_in; (void)out_size;
    const float* hist  = (const float*)d_in[0];
    const float* cand  = (const float*)d_in[2];
    const int*   numI  = (const int*)d_in[3];
    const int*   catC  = (const int*)d_in[4];
    const float* W     = (const float*)d_in[5];
    const float* codes = (const float*)d_in[6];
    float* out = (float*)d_out;

    static bool attr_set = false;
    if (!attr_set) {
        cudaFuncSetAttribute(k1_mma, cudaFuncAttributeMaxDynamicSharedMemorySize, K1_SMEM);
        attr_set = true;
    }

    kw_split<<<256, 256>>>(W);
    k1_mma<<<dim3(2, 400), 256, K1_SMEM>>>(hist);
    k2_kernel<<<BSZ, 256>>>(hist, codes, numI);
    k4_kernel<<<2 * BSZ, 256>>>(cand, catC, out);
}

// round 6
// speedup vs baseline: 2.1243x; 1.2420x over previous
#include <cuda_runtime.h>
#include <cuda_fp16.h>
#include <math.h>
#include <stdint.h>

#define BSZ   512
#define LEN   100
#define NCAND 64
#define DIM   256
#define KIN   32

typedef unsigned long long u64;

// Scratch (no allocations allowed)
__device__ float  g_proj[BSZ * LEN * DIM];          // 52.4 MB
__device__ float  g_inter[BSZ * KIN * DIM];         // 16.8 MB
__device__ float  g_scores[BSZ * KIN * LEN];        // 6.6 MB   [b][k][l]
__device__ __half g_a1[BSZ * 2 * KIN * 64];         // 4.2 MB   [b][h][k][64]
__device__ __half g_a2[BSZ * 2 * KIN * 64];         // 4.2 MB
__device__ __half g_h1[256 * 256];
__device__ __half g_h2[256 * 256];

// ---- packed fp32x2 helpers --------------------------------------------------
__device__ __forceinline__ u64 ffma2(u64 a, u64 b, u64 c) {
    u64 d;
    asm("fma.rn.f32x2 %0, %1, %2, %3;" : "=l"(d) : "l"(a), "l"(b), "l"(c));
    return d;
}
__device__ __forceinline__ u64 pack2(float lo, float hi) {
    u64 r;
    asm("mov.b64 %0, {%1, %2};" : "=l"(r) : "f"(lo), "f"(hi));
    return r;
}
__device__ __forceinline__ u64 packu(uint32_t a, uint32_t b) {
    u64 r;
    asm("mov.b64 %0, {%1, %2};" : "=l"(r) : "r"(a), "r"(b));
    return r;
}
__device__ __forceinline__ float2 unpack2(u64 v) {
    float2 r;
    asm("mov.b64 {%0, %1}, %2;" : "=f"(r.x), "=f"(r.y) : "l"(v));
    return r;
}

// ---- mma.sync helpers ---------------------------------------------------------
__device__ __forceinline__ uint32_t smem_u32(const void* p) {
    uint32_t a;
    asm("{ .reg .u64 t; cvta.to.shared.u64 t, %1; cvt.u32.u64 %0, t; }" : "=r"(a) : "l"(p));
    return a;
}
__device__ __forceinline__ void ldsm4(uint32_t* r, uint32_t addr) {
    asm volatile("ldmatrix.sync.aligned.m8n8.x4.shared.b16 {%0,%1,%2,%3}, [%4];"
                 : "=r"(r[0]), "=r"(r[1]), "=r"(r[2]), "=r"(r[3]) : "r"(addr) : "memory");
}
__device__ __forceinline__ void ldsm4t(uint32_t* r, uint32_t addr) {
    asm volatile("ldmatrix.sync.aligned.m8n8.x4.trans.shared.b16 {%0,%1,%2,%3}, [%4];"
                 : "=r"(r[0]), "=r"(r[1]), "=r"(r[2]), "=r"(r[3]) : "r"(addr) : "memory");
}
__device__ __forceinline__ void mma16816(float* d, const uint32_t* a, uint32_t b0, uint32_t b1) {
    asm volatile("mma.sync.aligned.m16n8k16.row.col.f32.f16.f16.f32 "
                 "{%0,%1,%2,%3}, {%4,%5,%6,%7}, {%8,%9}, {%0,%1,%2,%3};"
                 : "+f"(d[0]), "+f"(d[1]), "+f"(d[2]), "+f"(d[3])
                 : "r"(a[0]), "r"(a[1]), "r"(a[2]), "r"(a[3]), "r"(b0), "r"(b1));
}

#define SWZ(o) ((o) ^ (((o) >> 3) & 0x70))

__device__ __forceinline__ uint32_t h2_u32(__half a, __half b) {
    __half2 t(a, b);
    return *reinterpret_cast<uint32_t*>(&t);
}

// ---------------------------------------------------------------------------
// W split: W (fp32) -> 2 fp16 levels
// ---------------------------------------------------------------------------
__global__ void kw_split(const float* __restrict__ W) {
    const int i = blockIdx.x * 256 + threadIdx.x;
    const float a = W[i];
    const __half h1 = __float2half_rn(a);
    g_h1[i] = h1;
    g_h2[i] = __float2half_rn(a - __half2float(h1));
}

// ---------------------------------------------------------------------------
// K1: proj = tanh(hist @ W^T) via mma.sync fp16, 2-level split (3 passes).
// (unchanged from R5 — at HMMA floor)
// ---------------------------------------------------------------------------
#define A_OFF  0
#define B_OFF  32768
#define LVL    16384
#define K1_SMEM (65536 + 1024)

__global__ void __launch_bounds__(256, 2) k1_mma(const float* __restrict__ hist) {
    extern __shared__ char smem_raw[];
    const int tid = threadIdx.x;
    const int wid = tid >> 5;
    const int lane = tid & 31;
    const int warp_m = wid >> 2;
    const int warp_n = wid & 3;
    const int m0 = blockIdx.y * 128;
    const int n0 = blockIdx.x * 128;

    const uint32_t sb_raw = smem_u32(smem_raw);
    const uint32_t sb = (sb_raw + 1023u) & ~1023u;
    char* smem = smem_raw + (sb - sb_raw);

    const int g  = lane >> 3;
    const int rw = lane & 7;

    float acc[4][4][4];
#pragma unroll
    for (int mt = 0; mt < 4; mt++)
#pragma unroll
        for (int nt = 0; nt < 4; nt++)
#pragma unroll
            for (int i = 0; i < 4; i++) acc[mt][nt][i] = 0.f;

    for (int kc = 0; kc < 4; kc++) {
#pragma unroll
        for (int t = 0; t < 8; t++) {
            const int idx = tid + t * 256;
            const int r = idx >> 4, c4 = idx & 15;
            const float4 a = __ldg((const float4*)&hist[(size_t)(m0 + r) * 256 + kc * 64 + c4 * 4]);
            const __half h1x = __float2half_rn(a.x), h1y = __float2half_rn(a.y);
            const __half h1z = __float2half_rn(a.z), h1w = __float2half_rn(a.w);
            const __half h2x = __float2half_rn(a.x - __half2float(h1x));
            const __half h2y = __float2half_rn(a.y - __half2float(h1y));
            const __half h2z = __float2half_rn(a.z - __half2float(h1z));
            const __half h2w = __float2half_rn(a.w - __half2float(h1w));
            const uint32_t off = SWZ((uint32_t)(r * 128 + c4 * 8));
            *(uint2*)(smem + A_OFF + 0 * LVL + off) = make_uint2(h2_u32(h1x, h1y), h2_u32(h1z, h1w));
            *(uint2*)(smem + A_OFF + 1 * LVL + off) = make_uint2(h2_u32(h2x, h2y), h2_u32(h2z, h2w));
        }
        {
            const __half* gw[2] = {g_h1, g_h2};
#pragma unroll
            for (int lv = 0; lv < 2; lv++) {
#pragma unroll
                for (int t = 0; t < 4; t++) {
                    const int idx = tid + t * 256;
                    const int n = idx >> 3, u = idx & 7;
                    const uint4 v = *(const uint4*)&gw[lv][(size_t)(n0 + n) * 256 + kc * 64 + u * 8];
                    *(uint4*)(smem + B_OFF + lv * LVL + SWZ((uint32_t)(n * 128 + u * 16))) = v;
                }
            }
        }
        __syncthreads();

#pragma unroll
        for (int ks = 0; ks < 4; ks++) {
            const int k0 = ks * 16;
            uint32_t aoff[4], boff[2];
#pragma unroll
            for (int mt = 0; mt < 4; mt++) {
                const int row = warp_m * 64 + mt * 16 + ((g & 1) << 3) + rw;
                const int kk  = k0 + ((g >> 1) << 3);
                aoff[mt] = sb + A_OFF + SWZ((uint32_t)(row * 128 + kk * 2));
            }
#pragma unroll
            for (int nt2 = 0; nt2 < 2; nt2++) {
                const int row = warp_n * 32 + nt2 * 16 + ((g >> 1) << 3) + rw;
                const int kk  = k0 + ((g & 1) << 3);
                boff[nt2] = sb + B_OFF + SWZ((uint32_t)(row * 128 + kk * 2));
            }

            uint32_t a0[4][4], a1[4][4], b0[2][4], b1[2][4];
#pragma unroll
            for (int mt = 0; mt < 4; mt++) { ldsm4(a0[mt], aoff[mt]); ldsm4(a1[mt], aoff[mt] + LVL); }
#pragma unroll
            for (int nt2 = 0; nt2 < 2; nt2++) { ldsm4(b0[nt2], boff[nt2]); ldsm4(b1[nt2], boff[nt2] + LVL); }

#pragma unroll
            for (int mt = 0; mt < 4; mt++)
#pragma unroll
                for (int nt = 0; nt < 4; nt++) {
                    const int h = nt >> 1, q = (nt & 1) * 2;
                    mma16816(acc[mt][nt], a0[mt], b0[h][q], b0[h][q + 1]);
                    mma16816(acc[mt][nt], a0[mt], b1[h][q], b1[h][q + 1]);
                    mma16816(acc[mt][nt], a1[mt], b0[h][q], b0[h][q + 1]);
                }
        }
        __syncthreads();
    }

    const int gid = lane >> 2, tig = lane & 3;
#pragma unroll
    for (int mt = 0; mt < 4; mt++) {
#pragma unroll
        for (int nt = 0; nt < 4; nt++) {
            const int row = m0 + warp_m * 64 + mt * 16 + gid;
            const int col = n0 + warp_n * 32 + nt * 8 + tig * 2;
            float2 v0, v1;
            v0.x = tanhf(acc[mt][nt][0]); v0.y = tanhf(acc[mt][nt][1]);
            v1.x = tanhf(acc[mt][nt][2]); v1.y = tanhf(acc[mt][nt][3]);
            *(float2*)&g_proj[(size_t)row * 256 + col]       = v0;
            *(float2*)&g_proj[(size_t)(row + 8) * 256 + col] = v1;
        }
    }
}

// ---------------------------------------------------------------------------
// K2a: scores = g_proj @ codes^T   [M=51200, N=32, K=256], fp16 2-split mma.
// CTA tile 128x32, 4 warps (warp tile 32x32). Writes g_scores[b][k][l].
// ---------------------------------------------------------------------------
__global__ void __launch_bounds__(128) k2a_kernel(const float* __restrict__ codes) {
    __shared__ __align__(16) char Asm[2][16384];   // [lvl][128 rows][64 c] fp16
    __shared__ __align__(16) char Bsm[2][4096];    // [lvl][32 k][64 c] fp16

    const int tid = threadIdx.x;
    const int w = tid >> 5;
    const int lane = tid & 31;
    const int m0 = blockIdx.x * 128;
    const int g = lane >> 3, rw = lane & 7;
    const uint32_t sbA = smem_u32(Asm);
    const uint32_t sbB = smem_u32(Bsm);

    float acc[2][4][4];
#pragma unroll
    for (int mt = 0; mt < 2; mt++)
#pragma unroll
        for (int nt = 0; nt < 4; nt++)
#pragma unroll
            for (int i = 0; i < 4; i++) acc[mt][nt][i] = 0.f;

    for (int kc = 0; kc < 4; kc++) {
        // A: 128 rows x 64 c of proj, fp16 2-split, swizzled
#pragma unroll
        for (int t = 0; t < 16; t++) {
            const int idx = tid + t * 128;
            const int r = idx >> 4, c4 = idx & 15;
            const float4 a = __ldg((const float4*)&g_proj[(size_t)(m0 + r) * 256 + kc * 64 + c4 * 4]);
            const __half h1x = __float2half_rn(a.x), h1y = __float2half_rn(a.y);
            const __half h1z = __float2half_rn(a.z), h1w = __float2half_rn(a.w);
            const __half h2x = __float2half_rn(a.x - __half2float(h1x));
            const __half h2y = __float2half_rn(a.y - __half2float(h1y));
            const __half h2z = __float2half_rn(a.z - __half2float(h1z));
            const __half h2w = __float2half_rn(a.w - __half2float(h1w));
            const uint32_t off = SWZ((uint32_t)(r * 128 + c4 * 8));
            *(uint2*)(Asm[0] + off) = make_uint2(h2_u32(h1x, h1y), h2_u32(h1z, h1w));
            *(uint2*)(Asm[1] + off) = make_uint2(h2_u32(h2x, h2y), h2_u32(h2z, h2w));
        }
        // B: codes 32 k x 64 c, fp16 2-split, swizzled
#pragma unroll
        for (int t = 0; t < 4; t++) {
            const int idx = tid + t * 128;
            const int r = idx >> 4, c4 = idx & 15;
            const float4 a = __ldg((const float4*)&codes[(size_t)r * 256 + kc * 64 + c4 * 4]);
            const __half h1x = __float2half_rn(a.x), h1y = __float2half_rn(a.y);
            const __half h1z = __float2half_rn(a.z), h1w = __float2half_rn(a.w);
            const __half h2x = __float2half_rn(a.x - __half2float(h1x));
            const __half h2y = __float2half_rn(a.y - __half2float(h1y));
            const __half h2z = __float2half_rn(a.z - __half2float(h1z));
            const __half h2w = __float2half_rn(a.w - __half2float(h1w));
            const uint32_t off = SWZ((uint32_t)(r * 128 + c4 * 8));
            *(uint2*)(Bsm[0] + off) = make_uint2(h2_u32(h1x, h1y), h2_u32(h1z, h1w));
            *(uint2*)(Bsm[1] + off) = make_uint2(h2_u32(h2x, h2y), h2_u32(h2z, h2w));
        }
        __syncthreads();

#pragma unroll
        for (int ks = 0; ks < 4; ks++) {
            const int k0 = ks * 16;
            uint32_t aoff[2], boff[2];
#pragma unroll
            for (int mt = 0; mt < 2; mt++) {
                const int row = w * 32 + mt * 16 + ((g & 1) << 3) + rw;
                aoff[mt] = sbA + SWZ((uint32_t)(row * 128 + (k0 + ((g >> 1) << 3)) * 2));
            }
#pragma unroll
            for (int nt2 = 0; nt2 < 2; nt2++) {
                const int row = nt2 * 16 + ((g >> 1) << 3) + rw;
                boff[nt2] = sbB + SWZ((uint32_t)(row * 128 + (k0 + ((g & 1) << 3)) * 2));
            }
            uint32_t a0[2][4], a1[2][4], b0[2][4], b1[2][4];
#pragma unroll
            for (int mt = 0; mt < 2; mt++) { ldsm4(a0[mt], aoff[mt]); ldsm4(a1[mt], aoff[mt] + 16384); }
#pragma unroll
            for (int nt2 = 0; nt2 < 2; nt2++) { ldsm4(b0[nt2], boff[nt2]); ldsm4(b1[nt2], boff[nt2] + 4096); }
#pragma unroll
            for (int mt = 0; mt < 2; mt++)
#pragma unroll
                for (int nt = 0; nt < 4; nt++) {
                    const int h = nt >> 1, q = (nt & 1) * 2;
                    mma16816(acc[mt][nt], a0[mt], b0[h][q], b0[h][q + 1]);
                    mma16816(acc[mt][nt], a0[mt], b1[h][q], b1[h][q + 1]);
                    mma16816(acc[mt][nt], a1[mt], b0[h][q], b0[h][q + 1]);
                }
        }
        __syncthreads();
    }

    // epilogue: scatter to g_scores[b][k][l]
    const int gid = lane >> 2, tig = lane & 3;
#pragma unroll
    for (int mt = 0; mt < 2; mt++) {
#pragma unroll
        for (int nt = 0; nt < 4; nt++) {
            const int col = nt * 8 + tig * 2;
#pragma unroll
            for (int half = 0; half < 2; half++) {
                const int M = m0 + w * 32 + mt * 16 + gid + half * 8;
                const int b = M / 100, l = M - b * 100;
                float* dst = g_scores + (size_t)b * 3200 + l;
                dst[(size_t)col * 100]       = acc[mt][nt][half * 2];
                dst[(size_t)(col + 1) * 100] = acc[mt][nt][half * 2 + 1];
            }
        }
    }
}

// ---------------------------------------------------------------------------
// K2b: per-batch masked softmax over L; emit attn as fp16 2-level split,
// zero-padded to L=128 in layout [b][h=l>>6][k][l&63].
// ---------------------------------------------------------------------------
__global__ __launch_bounds__(256) void k2b_kernel(const int* __restrict__ numInt) {
    const int b = blockIdx.x;
    const int tid = threadIdx.x;
    const int w = tid >> 5;
    const int lane = tid & 31;

    __shared__ float sc[32][100];

    const float* src = g_scores + (size_t)b * 3200;
    for (int idx = tid; idx < 3200; idx += 256) ((float*)sc)[idx] = src[idx];
    __syncthreads();

    const int ni = numInt[b];
    for (int k = w; k < 32; k += 8) {
        if (k >= ni) {
            for (int l = lane; l < LEN; l += 32) sc[k][l] = 0.01f;
        } else {
            float m = -3.4e38f;
            for (int l = lane; l < LEN; l += 32) m = fmaxf(m, sc[k][l]);
#pragma unroll
            for (int off = 16; off; off >>= 1)
                m = fmaxf(m, __shfl_xor_sync(0xffffffffu, m, off));
            float s = 0.f;
            for (int l = lane; l < LEN; l += 32) {
                float e = expf(sc[k][l] - m);
                sc[k][l] = e;
                s += e;
            }
#pragma unroll
            for (int off = 16; off; off >>= 1) s += __shfl_xor_sync(0xffffffffu, s, off);
            for (int l = lane; l < LEN; l += 32) sc[k][l] = sc[k][l] / s;
        }
    }
    __syncthreads();

    // write splits, pad l in [100,128) with zeros
    for (int idx = tid; idx < 32 * 64; idx += 256) {
        const int k = idx >> 6;
        const int l2 = (idx & 63) * 2;
        float v0 = (l2 < 100) ? sc[k][l2] : 0.f;
        float v1 = (l2 + 1 < 100) ? sc[k][l2 + 1] : 0.f;
        const __half a1x = __float2half_rn(v0), a1y = __float2half_rn(v1);
        const __half a2x = __float2half_rn(v0 - __half2float(a1x));
        const __half a2y = __float2half_rn(v1 - __half2float(a1y));
        const int h = l2 >> 6, ll = l2 & 63;
        const size_t off = (size_t)b * 4096 + h * 2048 + k * 64 + ll;
        *(__half2*)&g_a1[off] = __half2(a1x, a1y);
        *(__half2*)&g_a2[off] = __half2(a2x, a2y);
    }
}

// ---------------------------------------------------------------------------
// K2c: interests = attn @ hist per batch  [M=32 k, N=256 d, K=128 l (padded)]
// A = attn fp16 split (from k2b), B = hist fp16 split inline, ldmatrix.trans.
// ---------------------------------------------------------------------------
__global__ void __launch_bounds__(128) k2c_kernel(const float* __restrict__ hist) {
    __shared__ __align__(16) char Asm[16384];  // [lvl][h][32 k][64 l] fp16, swizzled
    __shared__ __align__(16) char Bsm[32768];  // [lvl][panel][32 l][64 d] fp16, swizzled

    const int b = blockIdx.x;
    const int tid = threadIdx.x;
    const int w = tid >> 5;          // warp = d-panel
    const int lane = tid & 31;
    const int g = lane >> 3, rw = lane & 7;
    const uint32_t sbA = smem_u32(Asm);
    const uint32_t sbB = smem_u32(Bsm);

    // ---- copy attn splits into swizzled SMEM (rows = h*32+k, 64 l each)
    {
        const uint4* s1 = (const uint4*)(g_a1 + (size_t)b * 4096);
        const uint4* s2 = (const uint4*)(g_a2 + (size_t)b * 4096);
#pragma unroll
        for (int t = 0; t < 4; t++) {
            const int idx = tid + t * 128;           // 512 uint4 per level
            const int r = idx >> 3, c8 = idx & 7;
            const uint32_t off = SWZ((uint32_t)(r * 128 + c8 * 16));
            *(uint4*)(Asm + off)        = s1[idx];
            *(uint4*)(Asm + 8192 + off) = s2[idx];
        }
    }

    float acc[2][8][4];
#pragma unroll
    for (int mt = 0; mt < 2; mt++)
#pragma unroll
        for (int nt = 0; nt < 8; nt++)
#pragma unroll
            for (int i = 0; i < 4; i++) acc[mt][nt][i] = 0.f;

    const float* Hb = hist + (size_t)b * LEN * DIM;

    for (int ch = 0; ch < 4; ch++) {
        const int l0 = ch * 32;
        // ---- load hist chunk [32 l][256 d] fp32 -> fp16 2-split into panels
#pragma unroll
        for (int t = 0; t < 16; t++) {
            const int idx = tid + t * 128;
            const int lr = idx >> 6, c4 = idx & 63;  // row 0..31, float4 col 0..63
            const int l = l0 + lr;
            float4 a = make_float4(0.f, 0.f, 0.f, 0.f);
            if (l < LEN) a = __ldg((const float4*)&Hb[(size_t)l * 256 + c4 * 4]);
            const __half h1x = __float2half_rn(a.x), h1y = __float2half_rn(a.y);
            const __half h1z = __float2half_rn(a.z), h1w = __float2half_rn(a.w);
            const __half h2x = __float2half_rn(a.x - __half2float(h1x));
            const __half h2y = __float2half_rn(a.y - __half2float(h1y));
            const __half h2z = __float2half_rn(a.z - __half2float(h1z));
            const __half h2w = __float2half_rn(a.w - __half2float(h1w));
            const int d = c4 * 4;
            const int p = d >> 6, dcol = d & 63;
            const uint32_t off = p * 4096 + SWZ((uint32_t)(lr * 128 + dcol * 2));
            *(uint2*)(Bsm + off)         = make_uint2(h2_u32(h1x, h1y), h2_u32(h1z, h1w));
            *(uint2*)(Bsm + 16384 + off) = make_uint2(h2_u32(h2x, h2y), h2_u32(h2z, h2w));
        }
        __syncthreads();

#pragma unroll
        for (int ks2 = 0; ks2 < 2; ks2++) {
            const int kk = l0 + ks2 * 16;            // global l of this k-step
            const int half = kk >> 6, lloc = kk & 63;

            // A fragments (m16k16), 2 m-tiles x 2 levels
            uint32_t a0[2][4], a1[2][4];
#pragma unroll
            for (int mt = 0; mt < 2; mt++) {
                const int row = mt * 16 + ((g & 1) << 3) + rw;          // k index 0..31
                const uint32_t ao = SWZ((uint32_t)((half * 32 + row) * 128 + (lloc + ((g >> 1) << 3)) * 2));
                ldsm4(a0[mt], sbA + ao);
                ldsm4(a1[mt], sbA + 8192 + ao);
            }

            // B fragments via ldmatrix.trans, 4 n16-tiles x 2 levels
            const int trow = ks2 * 16 + (lane & 7) + ((lane >> 3) & 1) * 8;  // l-local 0..31
            const int tcolb = ((lane >> 4) & 1) * 8;
#pragma unroll
            for (int ntt = 0; ntt < 4; ntt++) {
                const uint32_t bo = w * 4096 + SWZ((uint32_t)(trow * 128 + (ntt * 16 + tcolb) * 2));
                uint32_t bl0[4], bl1[4];
                ldsm4t(bl0, sbB + bo);
                ldsm4t(bl1, sbB + 16384 + bo);
#pragma unroll
                for (int mt = 0; mt < 2; mt++) {
                    float* c0 = acc[mt][ntt * 2];
                    float* c1 = acc[mt][ntt * 2 + 1];
                    mma16816(c0, a0[mt], bl0[0], bl0[1]);
                    mma16816(c0, a0[mt], bl1[0], bl1[1]);
                    mma16816(c0, a1[mt], bl0[0], bl0[1]);
                    mma16816(c1, a0[mt], bl0[2], bl0[3]);
                    mma16816(c1, a0[mt], bl1[2], bl1[3]);
                    mma16816(c1, a1[mt], bl0[2], bl0[3]);
                }
            }
        }
        __syncthreads();
    }

    // ---- epilogue: write g_inter[b][k][d]
    const int gid = lane >> 2, tig = lane & 3;
    float* Ib = g_inter + (size_t)b * KIN * DIM;
#pragma unroll
    for (int mt = 0; mt < 2; mt++) {
#pragma unroll
        for (int nt = 0; nt < 8; nt++) {
            const int k = mt * 16 + gid;
            const int d = w * 64 + nt * 8 + tig * 2;
            *(float2*)&Ib[(size_t)k * 256 + d]       = make_float2(acc[mt][nt][0], acc[mt][nt][1]);
            *(float2*)&Ib[(size_t)(k + 8) * 256 + d] = make_float2(acc[mt][nt][2], acc[mt][nt][3]);
        }
    }
}

// ---------------------------------------------------------------------------
// K4: 2 blocks per batch (32 candidates): w -> dynK top-k mask -> user
// fp32 exact (top-k load-bearing), LDS.128 broadcast loads.
// ---------------------------------------------------------------------------
__global__ __launch_bounds__(256) void k4_kernel(const float* __restrict__ cand,
                                                 const int* __restrict__ catCnt,
                                                 float* __restrict__ out) {
    const int b = blockIdx.x >> 1;
    const int nbase = (blockIdx.x & 1) * 32;
    const int tid = threadIdx.x;
    const int w = tid >> 5;
    const int lane = tid & 31;

    __shared__ __align__(16) float inter_sm[32 * 256];
    __shared__ __align__(16) float row_sm[8 * 256];
    __shared__ float partial_sm[8][8][32];
    __shared__ float wfull_sm[8][32];
    __shared__ __align__(16) float wmask_sm[32][32];

    const float* Ib = g_inter + (size_t)b * KIN * DIM;
    {
        const float4* src = (const float4*)Ib;
        float4* dst = (float4*)inter_sm;
#pragma unroll
        for (int t = 0; t < 8; t++) dst[tid + t * 256] = src[tid + t * 256];
    }
    __syncthreads();

    u64 ireg2[16];
    {
        const u64* ibase = (const u64*)&inter_sm[lane * 256 + w * 32];
#pragma unroll
        for (int j = 0; j < 16; j++) ireg2[j] = ibase[j];
    }

    const int cc = catCnt[b];
    int dynK = (int)ceilf(log2f(8.0f * (float)cc));
    dynK = dynK < 1 ? 1 : (dynK > 32 ? 32 : dynK);

    const float* Cb = cand + (size_t)b * NCAND * DIM + (size_t)nbase * DIM;
    for (int n0 = 0; n0 < 32; n0 += 8) {
        const float4* src = (const float4*)(Cb + (size_t)n0 * DIM);
        float4* dst = (float4*)row_sm;
        dst[tid] = src[tid];
        dst[tid + 256] = src[tid + 256];
        __syncthreads();

        u64 p[8];
#pragma unroll
        for (int r = 0; r < 8; r++) p[r] = 0ull;
        const uint4* rbase4 = (const uint4*)row_sm;   // row r: 64 uint4
#pragma unroll
        for (int j4 = 0; j4 < 8; j4++) {
            const u64 iv0 = ireg2[j4 * 2], iv1 = ireg2[j4 * 2 + 1];
            const int coff = w * 8 + j4;
#pragma unroll
            for (int r = 0; r < 8; r++) {
                const uint4 v = rbase4[r * 64 + coff];
                p[r] = ffma2(iv0, packu(v.x, v.y), p[r]);
                p[r] = ffma2(iv1, packu(v.z, v.w), p[r]);
            }
        }
#pragma unroll
        for (int r = 0; r < 8; r++) {
            float2 t = unpack2(p[r]);
            partial_sm[w][r][lane] = t.x + t.y;
        }
        __syncthreads();

        {
            const int k = tid & 31, r = tid >> 5;
            float s = 0.f;
#pragma unroll
            for (int ww = 0; ww < 8; ww++) s += partial_sm[ww][r][k];
            wfull_sm[r][k] = s;
        }
        __syncthreads();

        {
            const float wi = wfull_sm[w][lane];
            int rank = 0;
#pragma unroll
            for (int j = 0; j < 32; j++) {
                const float wj = __shfl_sync(0xffffffffu, wi, j);
                rank += (wj > wi) || (wj == wi && j < lane);
            }
            wmask_sm[lane][n0 + w] = (rank < dynK) ? wi : 0.f;
        }
        __syncthreads();
    }

    u64 accU[16];
#pragma unroll
    for (int j = 0; j < 16; j++) accU[j] = 0ull;

#pragma unroll
    for (int k = 0; k < 32; k++) {
        const float iv = inter_sm[k * 256 + tid];
        const u64 ivv = pack2(iv, iv);
        const uint4* wrow4 = (const uint4*)&wmask_sm[k][0];
#pragma unroll
        for (int j4 = 0; j4 < 8; j4++) {
            const uint4 v = wrow4[j4];
            accU[j4 * 2]     = ffma2(ivv, packu(v.x, v.y), accU[j4 * 2]);
            accU[j4 * 2 + 1] = ffma2(ivv, packu(v.z, v.w), accU[j4 * 2 + 1]);
        }
    }

    float* Ob = out + (size_t)b * NCAND * DIM + (size_t)nbase * DIM;
#pragma unroll
    for (int j = 0; j < 16; j++) {
        float2 t = unpack2(accU[j]);
        Ob[(size_t)(2 * j) * 256 + tid]     = t.x;
        Ob[(size_t)(2 * j + 1) * 256 + tid] = t.y;
    }
}

// ---------------------------------------------------------------------------
extern "C" void kernel_launch(void* const* d_in, const int* in_sizes, int n_in,
                              void* d_out, int out_size) {
    (void)in_sizes; (void)n_in; (void)out_size;
    const float* hist  = (const float*)d_in[0];
    const float* cand  = (const float*)d_in[2];
    const int*   numI  = (const int*)d_in[3];
    const int*   catC  = (const int*)d_in[4];
    const float* W     = (const float*)d_in[5];
    const float* codes = (const float*)d_in[6];
    float* out = (float*)d_out;

    static bool attr_set = false;
    if (!attr_set) {
        cudaFuncSetAttribute(k1_mma, cudaFuncAttributeMaxDynamicSharedMemorySize, K1_SMEM);
        attr_set = true;
    }

    kw_split<<<256, 256>>>(W);
    k1_mma<<<dim3(2, 400), 256, K1_SMEM>>>(hist);
    k2a_kernel<<<400, 128>>>(codes);
    k2b_kernel<<<BSZ, 256>>>(numI);
    k2c_kernel<<<BSZ, 128>>>(hist);
    k4_kernel<<<2 * BSZ, 256>>>(cand, catC, out);
}